// round 10
// baseline (speedup 1.0000x reference)
#include <cuda_runtime.h>
#include <math.h>
#include <stdint.h>

#define T_SEQ 4096
#define DIM   2048
#define NH    16
#define HD    128
#define GK    2048

// ---------------- scratch (no allocations allowed) ----------------
__device__ float g_q[T_SEQ * DIM];
__device__ float g_k[T_SEQ * DIM];
__device__ float g_v[T_SEQ * DIM];
__device__ float g_o[T_SEQ * DIM];       // flash output, k-permuted + rounded
__device__ float g_kp[T_SEQ * DIM];      // K rounded, d-permuted (key-major)
__device__ float g_vt[DIM * T_SEQ];      // V rounded, [h][d][t'], t' key-permuted
__device__ float g_xr[T_SEQ * DIM];      // x rounded + k-permuted
__device__ float g_w[4 * DIM * DIM];     // Wt[N,K] rounded + k-permuted, 4 slabs

// =================== helpers ===================
__device__ __forceinline__ uint32_t smem_u32(const void* p) {
    uint32_t a;
    asm("{ .reg .u64 t; cvta.to.shared.u64 t, %1; cvt.u32.u64 %0, t; }" : "=r"(a) : "l"(p));
    return a;
}
__device__ __forceinline__ uint32_t tf32b(float x) {
    uint32_t r;
    asm("cvt.rna.tf32.f32 %0, %1;" : "=r"(r) : "f"(x));
    return r;
}
__device__ __forceinline__ float tf32f(float x) { return __uint_as_float(tf32b(x)); }
__device__ __forceinline__ void cpa16(uint32_t saddr, const void* g) {
    asm volatile("cp.async.cg.shared.global [%0], [%1], 16;" :: "r"(saddr), "l"(g));
}
__device__ __forceinline__ void mma8(float* d, const uint32_t* a, uint32_t b0, uint32_t b1) {
    asm volatile(
        "mma.sync.aligned.m16n8k8.row.col.f32.tf32.tf32.f32 "
        "{%0,%1,%2,%3}, {%4,%5,%6,%7}, {%8,%9}, {%0,%1,%2,%3};"
        : "+f"(d[0]), "+f"(d[1]), "+f"(d[2]), "+f"(d[3])
        : "r"(a[0]), "r"(a[1]), "r"(a[2]), "r"(a[3]), "r"(b0), "r"(b1));
}

// =================== permute k within 8-groups + round (src = unpermuted) ===================
__global__ __launch_bounds__(256) void permute_k(const float* __restrict__ S,
                                                 float* __restrict__ D)
{
    int idx = blockIdx.x * 256 + threadIdx.x;
    int t = idx >> 11;
    int c = idx & 2047;
    int r = c & 7;
    int src = (c & ~7) + (r >> 1) + ((r & 1) << 2);
    D[idx] = tf32f(S[(size_t)t * DIM + src]);
}

// =================== transpose W[K,N] -> Wt[N,K] with k-permutation + rounding ===================
__global__ __launch_bounds__(256) void transpose_w(const float* __restrict__ W0,
                                                   const float* __restrict__ W1,
                                                   const float* __restrict__ W2,
                                                   const float* __restrict__ W3,
                                                   float* __restrict__ Wt)
{
    __shared__ float t[32][33];
    const int z = blockIdx.z;
    const float* W = (z == 0) ? W0 : (z == 1) ? W1 : (z == 2) ? W2 : W3;
    float* D = Wt + (size_t)z * DIM * DIM;
    const int k0 = blockIdx.x * 32;
    const int n0 = blockIdx.y * 32;
    const int tx = threadIdx.x & 31, ty = threadIdx.x >> 5;
#pragma unroll
    for (int i = 0; i < 4; i++)
        t[ty + 8 * i][tx] = W[(size_t)(k0 + ty + 8 * i) * DIM + n0 + tx];
    __syncthreads();
    const int ksrc = (tx & ~7) + ((tx & 7) >> 1) + ((tx & 1) << 2);
#pragma unroll
    for (int i = 0; i < 4; i++)
        D[(size_t)(n0 + ty + 8 * i) * GK + k0 + tx] = tf32f(t[ksrc][ty + 8 * i]);
}

// =================== mma.sync tf32 GEMM (BK=32, both operands K-major k-permuted) ===================
#define BK        32
#define NSTG      3
#define A_ROWB    144                 // 36 floats (32 + 4 pad)
#define B_ROWB    144
#define A_BYTES   (128 * A_ROWB)      // 18432
#define B_BYTES   (128 * B_ROWB)      // 18432
#define STG_BYTES (A_BYTES + B_BYTES) // 36864
#define NT        (GK / BK)           // 64

__device__ __forceinline__ void load_stage(uint32_t sb, const float* __restrict__ A,
                                           const float* __restrict__ Wt,
                                           int m0, int n0, int kt, int tid) {
    uint32_t st = sb + (uint32_t)(kt % NSTG) * STG_BYTES;
    const int k0 = kt * BK;
#pragma unroll
    for (int i = 0; i < 4; i++) {
        int id = tid + i * 256;            // A: 128 rows x 8 chunks
        int row = id >> 3, seg = id & 7;
        cpa16(st + row * A_ROWB + seg * 16,
              A + (size_t)(m0 + row) * GK + k0 + seg * 4);
    }
#pragma unroll
    for (int i = 0; i < 4; i++) {
        int id = tid + i * 256;            // B: 128 n-rows x 8 chunks
        int row = id >> 3, seg = id & 7;
        cpa16(st + A_BYTES + row * B_ROWB + seg * 16,
              Wt + (size_t)(n0 + row) * GK + k0 + seg * 4);
    }
}

__global__ __launch_bounds__(256) void gemm_mma(const float* __restrict__ A,
                                                const float* __restrict__ Wr,
                                                const float* __restrict__ b0p,
                                                const float* __restrict__ b1p,
                                                const float* __restrict__ b2p,
                                                float* __restrict__ C0,
                                                float* __restrict__ C1,
                                                float* __restrict__ C2)
{
    extern __shared__ __align__(16) char smem[];
    const uint32_t sb = smem_u32(smem);
    const int z = blockIdx.z;
    const float* Wt   = Wr + (size_t)z * DIM * DIM;
    const float* bias = (z == 0) ? b0p : (z == 1) ? b1p : b2p;
    float* C          = (z == 0) ? C0  : (z == 1) ? C1  : C2;

    const int tid  = threadIdx.x;
    const int lane = tid & 31;
    const int wid  = tid >> 5;
    const int wm   = (wid >> 1) * 32;
    const int wn   = (wid & 1) * 64;
    const int n0   = blockIdx.x * 128;
    const int m0   = blockIdx.y * 128;

    const int gq = lane >> 2;
    const int tg = lane & 3;

    float acc[2][8][4];
#pragma unroll
    for (int mi = 0; mi < 2; mi++)
#pragma unroll
        for (int ni = 0; ni < 8; ni++)
#pragma unroll
            for (int r = 0; r < 4; r++) acc[mi][ni][r] = 0.f;

#pragma unroll
    for (int kt = 0; kt < NSTG; kt++) {
        load_stage(sb, A, Wt, m0, n0, kt, tid);
        asm volatile("cp.async.commit_group;" ::: "memory");
    }

    for (int kt = 0; kt < NT; kt++) {
        asm volatile("cp.async.wait_group %0;" :: "n"(NSTG - 1) : "memory");
        __syncthreads();

        const float* smf = (const float*)(smem + (kt % NSTG) * STG_BYTES);
        const float* bsf = (const float*)(smem + (kt % NSTG) * STG_BYTES + A_BYTES);

#pragma unroll
        for (int ks = 0; ks < BK; ks += 8) {
            uint32_t afr[2][4];
#pragma unroll
            for (int mi = 0; mi < 2; mi++) {
                int r0 = wm + mi * 16 + gq;
                float2 a0 = *(const float2*)(smf + r0 * 36 + ks + 2 * tg);
                float2 a1 = *(const float2*)(smf + (r0 + 8) * 36 + ks + 2 * tg);
                afr[mi][0] = __float_as_uint(a0.x);
                afr[mi][1] = __float_as_uint(a1.x);
                afr[mi][2] = __float_as_uint(a0.y);
                afr[mi][3] = __float_as_uint(a1.y);
            }
#pragma unroll
            for (int ni = 0; ni < 8; ni++) {
                int nb = wn + ni * 8 + gq;
                float2 bb = *(const float2*)(bsf + nb * 36 + ks + 2 * tg);
                mma8(acc[0][ni], afr[0], __float_as_uint(bb.x), __float_as_uint(bb.y));
                mma8(acc[1][ni], afr[1], __float_as_uint(bb.x), __float_as_uint(bb.y));
            }
        }
        __syncthreads();

        if (kt + NSTG < NT)
            load_stage(sb, A, Wt, m0, n0, kt + NSTG, tid);
        asm volatile("cp.async.commit_group;" ::: "memory");
    }

#pragma unroll
    for (int mi = 0; mi < 2; mi++) {
        int row = m0 + wm + mi * 16 + gq;
#pragma unroll
        for (int ni = 0; ni < 8; ni++) {
            int col = n0 + wn + ni * 8 + 2 * tg;
            float2 bz = *(const float2*)(bias + col);
            float2 v0, v1;
            v0.x = acc[mi][ni][0] + bz.x; v0.y = acc[mi][ni][1] + bz.y;
            v1.x = acc[mi][ni][2] + bz.x; v1.y = acc[mi][ni][3] + bz.y;
            *(float2*)(C + (size_t)row * DIM + col)       = v0;
            *(float2*)(C + (size_t)(row + 8) * DIM + col) = v1;
        }
    }
}

// ---------------- RMSNorm + RoPE ----------------
// grid.y==0: Q in-place, rounded (natural order, feeds flash A-frags)
// grid.y==1: K -> Kp, rounded + k-permuted (feeds flash B-frags via LDS.64)
__global__ __launch_bounds__(256) void rmsnorm_rope2(float* __restrict__ qb,
                                                     float* __restrict__ kb,
                                                     float* __restrict__ kp,
                                                     const float* __restrict__ gqw,
                                                     const float* __restrict__ gkw,
                                                     const float* __restrict__ freqs)
{
    const int t = blockIdx.x;
    const int isk = blockIdx.y;
    float* row = (isk ? kb : qb) + (size_t)t * DIM;
    const float* g = isk ? gkw : gqw;

    float ss = 0.f;
    for (int i = threadIdx.x; i < DIM; i += 256) {
        float v = row[i];
        ss += v * v;
    }
#pragma unroll
    for (int off = 16; off; off >>= 1) ss += __shfl_xor_sync(0xFFFFFFFFu, ss, off);

    __shared__ float red[8];
    __shared__ float stot;
    if ((threadIdx.x & 31) == 0) red[threadIdx.x >> 5] = ss;
    __syncthreads();
    if (threadIdx.x == 0) {
        float tot = 0.f;
#pragma unroll
        for (int i = 0; i < 8; i++) tot += red[i];
        stot = tot;
    }
    __syncthreads();

    const float scale = rsqrtf(stot * (1.f / DIM) + 1e-6f);
    float* krow = kp + (size_t)t * DIM;

    for (int p = threadIdx.x; p < DIM / 2; p += 256) {
        int e   = 2 * p;
        int pin = p & 63;
        float ang = freqs[(size_t)t * 64 + pin];
        float c, s;
        sincosf(ang, &s, &c);
        float x0 = row[e]     * scale * g[e];
        float x1 = row[e + 1] * scale * g[e + 1];
        float y0 = tf32f(x0 * c - x1 * s);
        float y1 = tf32f(x0 * s + x1 * c);
        if (!isk) {
            row[e]     = y0;
            row[e + 1] = y1;
        } else {
            int base = e & ~7;
            int s0 = e & 7, s1 = s0 + 1;
            krow[base + (((s0 & 3) << 1) | (s0 >> 2))] = y0;
            krow[base + (((s1 & 3) << 1) | (s1 >> 2))] = y1;
        }
    }
}

// ---------------- transpose V -> Vt[h][d][t'] with key-permutation + rounding ----------------
__global__ __launch_bounds__(256) void transpose_v(const float* __restrict__ V,
                                                   float* __restrict__ Vt)
{
    __shared__ float t[32][33];
    const int t0 = blockIdx.x * 32;
    const int d0 = blockIdx.y * 32;
    const int tx = threadIdx.x & 31, ty = threadIdx.x >> 5;
#pragma unroll
    for (int i = 0; i < 4; i++)
        t[ty + 8 * i][tx] = V[(size_t)(t0 + ty + 8 * i) * DIM + d0 + tx];
    __syncthreads();
    const int tperm = (tx & ~7) + ((tx & 7) >> 1) + ((tx & 1) << 2);
#pragma unroll
    for (int i = 0; i < 4; i++)
        Vt[(size_t)(d0 + ty + 8 * i) * T_SEQ + t0 + tx] = tf32f(t[tperm][ty + 8 * i]);
}

// ---------------- causal flash attention via mma.sync tf32 ----------------
#define FA_QT  128
#define FA_KT  64
#define Q_LD   132
#define K_LD   136
#define V_LDW  72
#define SM_Q   0
#define SM_KT  (FA_QT * Q_LD)
#define K_BUF  (FA_KT * K_LD)
#define SM_V   (SM_KT + 2 * K_BUF)
#define V_BUF  (HD * V_LDW)
#define FA_SM_FLOATS (SM_V + 2 * V_BUF)
#define FA_SM_BYTES  (FA_SM_FLOATS * 4)

__device__ __forceinline__ void fa_load_kv(uint32_t sb, const float* __restrict__ Kp,
                                           const float* __restrict__ Vt,
                                           int h, int j, int buf, int tid) {
    const int k0 = j * FA_KT;
    uint32_t kbb = sb + (uint32_t)(SM_KT + buf * K_BUF) * 4;
    uint32_t vbb = sb + (uint32_t)(SM_V + buf * V_BUF) * 4;
#pragma unroll
    for (int i = 0; i < 8; i++) {
        int id = tid + i * 256;
        int key = id >> 5, c = id & 31;
        cpa16(kbb + (uint32_t)(key * K_LD + c * 4) * 4,
              Kp + (size_t)(k0 + key) * DIM + h * HD + c * 4);
    }
#pragma unroll
    for (int i = 0; i < 8; i++) {
        int id = tid + i * 256;
        int d = id >> 4, c = id & 15;
        cpa16(vbb + (uint32_t)(d * V_LDW + c * 4) * 4,
              Vt + (size_t)(h * HD + d) * T_SEQ + k0 + c * 4);
    }
}

__global__ __launch_bounds__(256) void flash_mma(const float* __restrict__ Q,
                                                 const float* __restrict__ Kp_g,
                                                 const float* __restrict__ Vt_g,
                                                 float* __restrict__ O)
{
    extern __shared__ float sm[];
    const uint32_t sb = smem_u32(sm);
    const int qt = gridDim.x - 1 - blockIdx.x;
    const int h  = blockIdx.y;
    const int q0 = qt * FA_QT;
    const int tid  = threadIdx.x;
    const int lane = tid & 31, wid = tid >> 5;
    const int gq = lane >> 2, tg = lane & 3;
    const int wrow = wid * 16;
    const int nkt = 2 * qt + 2;
    const float scale = 0.08838834764831845f;

    for (int idx = tid; idx < FA_QT * 32; idx += 256) {
        int r = idx >> 5, c4 = (idx & 31) * 4;
        float4 v = *(const float4*)(Q + (size_t)(q0 + r) * DIM + h * HD + c4);
        float* dst = sm + SM_Q + r * Q_LD + c4;
        dst[0] = v.x; dst[1] = v.y; dst[2] = v.z; dst[3] = v.w;
    }

    fa_load_kv(sb, Kp_g, Vt_g, h, 0, 0, tid);
    asm volatile("cp.async.commit_group;" ::: "memory");
    __syncthreads();

    const float* Qp  = sm + SM_Q + (wrow + gq) * Q_LD;
    const float* Qp8 = Qp + 8 * Q_LD;
    uint32_t qfr[16][4];
#pragma unroll
    for (int ks = 0; ks < 16; ks++) {
        qfr[ks][0] = __float_as_uint(Qp [ks * 8 + tg]);
        qfr[ks][1] = __float_as_uint(Qp8[ks * 8 + tg]);
        qfr[ks][2] = __float_as_uint(Qp [ks * 8 + tg + 4]);
        qfr[ks][3] = __float_as_uint(Qp8[ks * 8 + tg + 4]);
    }

    float oacc[16][4];
#pragma unroll
    for (int nt = 0; nt < 16; nt++)
#pragma unroll
        for (int r = 0; r < 4; r++) oacc[nt][r] = 0.f;

    float m0 = -1e30f, m1 = -1e30f, l0 = 0.f, l1 = 0.f;
    const int r0 = q0 + wrow + gq, r1 = r0 + 8;

    for (int j = 0; j < nkt; j++) {
        if (j + 1 < nkt)
            fa_load_kv(sb, Kp_g, Vt_g, h, j + 1, (j + 1) & 1, tid);
        asm volatile("cp.async.commit_group;" ::: "memory");
        asm volatile("cp.async.wait_group 1;" ::: "memory");
        __syncthreads();

        const int buf = j & 1;
        const int k0 = j * FA_KT;
        const float* Kpb = sm + SM_KT + buf * K_BUF;
        const float* Vpb = sm + SM_V + buf * V_BUF;

        float sacc[8][4];
#pragma unroll
        for (int nt = 0; nt < 8; nt++)
#pragma unroll
            for (int r = 0; r < 4; r++) sacc[nt][r] = 0.f;

#pragma unroll
        for (int ks = 0; ks < 16; ks++) {
#pragma unroll
            for (int nt = 0; nt < 8; nt++) {
                float2 kb = *(const float2*)(Kpb + (nt * 8 + gq) * K_LD + ks * 8 + 2 * tg);
                mma8(sacc[nt], qfr[ks], __float_as_uint(kb.x), __float_as_uint(kb.y));
            }
        }

        const bool diag = (k0 + FA_KT - 1 > q0);
        float mx0 = -1e30f, mx1 = -1e30f;
#pragma unroll
        for (int nt = 0; nt < 8; nt++) {
            int c0 = k0 + nt * 8 + 2 * tg;
            float s0 = sacc[nt][0] * scale, s1 = sacc[nt][1] * scale;
            float s2 = sacc[nt][2] * scale, s3 = sacc[nt][3] * scale;
            if (diag) {
                if (c0     > r0) s0 = -1e30f;
                if (c0 + 1 > r0) s1 = -1e30f;
                if (c0     > r1) s2 = -1e30f;
                if (c0 + 1 > r1) s3 = -1e30f;
            }
            mx0 = fmaxf(mx0, fmaxf(s0, s1));
            mx1 = fmaxf(mx1, fmaxf(s2, s3));
            sacc[nt][0] = s0; sacc[nt][1] = s1; sacc[nt][2] = s2; sacc[nt][3] = s3;
        }
        mx0 = fmaxf(mx0, __shfl_xor_sync(0xFFFFFFFFu, mx0, 1));
        mx0 = fmaxf(mx0, __shfl_xor_sync(0xFFFFFFFFu, mx0, 2));
        mx1 = fmaxf(mx1, __shfl_xor_sync(0xFFFFFFFFu, mx1, 1));
        mx1 = fmaxf(mx1, __shfl_xor_sync(0xFFFFFFFFu, mx1, 2));

        const float mn0 = fmaxf(m0, mx0), mn1 = fmaxf(m1, mx1);
        const float f0 = __expf(m0 - mn0), f1 = __expf(m1 - mn1);
        m0 = mn0; m1 = mn1;

        float rs0 = 0.f, rs1 = 0.f;
#pragma unroll
        for (int nt = 0; nt < 8; nt++) {
            float e0 = __expf(sacc[nt][0] - mn0);
            float e1 = __expf(sacc[nt][1] - mn0);
            float e2 = __expf(sacc[nt][2] - mn1);
            float e3 = __expf(sacc[nt][3] - mn1);
            rs0 += e0 + e1; rs1 += e2 + e3;
            sacc[nt][0] = __uint_as_float(tf32b(e0));
            sacc[nt][1] = __uint_as_float(tf32b(e1));
            sacc[nt][2] = __uint_as_float(tf32b(e2));
            sacc[nt][3] = __uint_as_float(tf32b(e3));
        }
        rs0 += __shfl_xor_sync(0xFFFFFFFFu, rs0, 1);
        rs0 += __shfl_xor_sync(0xFFFFFFFFu, rs0, 2);
        rs1 += __shfl_xor_sync(0xFFFFFFFFu, rs1, 1);
        rs1 += __shfl_xor_sync(0xFFFFFFFFu, rs1, 2);
        l0 = l0 * f0 + rs0;
        l1 = l1 * f1 + rs1;

#pragma unroll
        for (int nt = 0; nt < 16; nt++) {
            oacc[nt][0] *= f0; oacc[nt][1] *= f0;
            oacc[nt][2] *= f1; oacc[nt][3] *= f1;
        }

        const int src0 = (lane & 28) | (tg >> 1);
        const int src2 = src0 + 2;
#pragma unroll
        for (int s = 0; s < 8; s++) {
            float w0 = __shfl_sync(0xFFFFFFFFu, sacc[s][0], src0);
            float w1 = __shfl_sync(0xFFFFFFFFu, sacc[s][1], src0);
            float w2 = __shfl_sync(0xFFFFFFFFu, sacc[s][2], src0);
            float w3 = __shfl_sync(0xFFFFFFFFu, sacc[s][3], src0);
            float w4 = __shfl_sync(0xFFFFFFFFu, sacc[s][0], src2);
            float w5 = __shfl_sync(0xFFFFFFFFu, sacc[s][1], src2);
            float w6 = __shfl_sync(0xFFFFFFFFu, sacc[s][2], src2);
            float w7 = __shfl_sync(0xFFFFFFFFu, sacc[s][3], src2);
            uint32_t af[4];
            af[0] = __float_as_uint((tg & 1) ? w1 : w0);
            af[1] = __float_as_uint((tg & 1) ? w3 : w2);
            af[2] = __float_as_uint((tg & 1) ? w5 : w4);
            af[3] = __float_as_uint((tg & 1) ? w7 : w6);
#pragma unroll
            for (int nt = 0; nt < 16; nt++) {
                float2 vb = *(const float2*)(Vpb + (nt * 8 + gq) * V_LDW + s * 8 + 2 * tg);
                mma8(oacc[nt], af, __float_as_uint(vb.x), __float_as_uint(vb.y));
            }
        }
        __syncthreads();
    }

    // epilogue: write k-PERMUTED + rounded (feeds Wo GEMM A-frags as LDS.64)
    const float inv0 = 1.f / l0, inv1 = 1.f / l1;
    const int d0 = (tg & 1) * 4 + (tg >> 1);   // dest of source col 2tg within 8-group
#pragma unroll
    for (int nt = 0; nt < 16; nt++) {
        int cb = h * HD + nt * 8;
        O[(size_t)r0 * DIM + cb + d0]     = tf32f(oacc[nt][0] * inv0);
        O[(size_t)r0 * DIM + cb + d0 + 2] = tf32f(oacc[nt][1] * inv0);
        O[(size_t)r1 * DIM + cb + d0]     = tf32f(oacc[nt][2] * inv1);
        O[(size_t)r1 * DIM + cb + d0 + 2] = tf32f(oacc[nt][3] * inv1);
    }
}

// ---------------- launch ----------------
extern "C" void kernel_launch(void* const* d_in, const int* in_sizes, int n_in,
                              void* d_out, int out_size)
{
    (void)in_sizes; (void)n_in; (void)out_size;
    const float* x     = (const float*)d_in[0];
    const float* freqs = (const float*)d_in[1];
    const float* Wq    = (const float*)d_in[2];
    const float* bq    = (const float*)d_in[3];
    const float* Wk    = (const float*)d_in[4];
    const float* bk    = (const float*)d_in[5];
    const float* Wv    = (const float*)d_in[6];
    const float* bv    = (const float*)d_in[7];
    const float* Wo    = (const float*)d_in[8];
    const float* bo    = (const float*)d_in[9];
    const float* gq    = (const float*)d_in[10];
    const float* gk    = (const float*)d_in[11];

    float *q, *k, *v, *o, *kp, *vt, *xr, *w;
    cudaGetSymbolAddress((void**)&q,  g_q);
    cudaGetSymbolAddress((void**)&k,  g_k);
    cudaGetSymbolAddress((void**)&v,  g_v);
    cudaGetSymbolAddress((void**)&o,  g_o);
    cudaGetSymbolAddress((void**)&kp, g_kp);
    cudaGetSymbolAddress((void**)&vt, g_vt);
    cudaGetSymbolAddress((void**)&xr, g_xr);
    cudaGetSymbolAddress((void**)&w,  g_w);

    const int gsm = NSTG * STG_BYTES;   // 110592
    cudaFuncSetAttribute(gemm_mma, cudaFuncAttributeMaxDynamicSharedMemorySize, gsm);
    cudaFuncSetAttribute(flash_mma, cudaFuncAttributeMaxDynamicSharedMemorySize, FA_SM_BYTES);

    // pre-passes: x rounded+permuted; weights transposed+permuted+rounded
    permute_k<<<T_SEQ * DIM / 256, 256>>>(x, xr);
    transpose_w<<<dim3(GK / 32, DIM / 32, 4), 256>>>(Wq, Wk, Wv, Wo, w);

    dim3 qkvgrid(DIM / 128, T_SEQ / 128, 3);
    gemm_mma<<<qkvgrid, 256, gsm>>>(xr, w, bq, bk, bv, q, k, v);

    rmsnorm_rope2<<<dim3(T_SEQ, 2), 256>>>(q, k, kp, gq, gk, freqs);

    transpose_v<<<dim3(T_SEQ / 32, DIM / 32), 256>>>(v, vt);

    flash_mma<<<dim3(T_SEQ / FA_QT, NH), 256, FA_SM_BYTES>>>(q, kp, vt, o);

    dim3 ogrid(DIM / 128, T_SEQ / 128, 1);
    gemm_mma<<<ogrid, 256, gsm>>>(o, w + 3 * DIM * DIM, bo, bo, bo,
                                  (float*)d_out, (float*)d_out, (float*)d_out);
}

// round 11
// speedup vs baseline: 1.1565x; 1.1565x over previous
#include <cuda_runtime.h>
#include <math.h>
#include <stdint.h>

#define T_SEQ 4096
#define DIM   2048
#define NH    16
#define HD    128
#define GK    2048

// ---------------- scratch (no allocations allowed) ----------------
__device__ float g_q[T_SEQ * DIM];
__device__ float g_k[T_SEQ * DIM];
__device__ float g_v[T_SEQ * DIM];
__device__ float g_o[T_SEQ * DIM];       // flash output, rounded (natural order)
__device__ float g_kp[T_SEQ * DIM];      // K rounded, d-permuted (key-major)
__device__ float g_vt[DIM * T_SEQ];      // V rounded, [h][d][t'], t' key-permuted
__device__ float g_xr[T_SEQ * DIM];      // tf32-rounded x (natural order)
__device__ float g_w[4 * DIM * DIM];     // tf32-rounded Wq,Wk,Wv,Wo (natural [K,N])

// =================== helpers ===================
__device__ __forceinline__ uint32_t smem_u32(const void* p) {
    uint32_t a;
    asm("{ .reg .u64 t; cvta.to.shared.u64 t, %1; cvt.u32.u64 %0, t; }" : "=r"(a) : "l"(p));
    return a;
}
__device__ __forceinline__ uint32_t tf32b(float x) {
    uint32_t r;
    asm("cvt.rna.tf32.f32 %0, %1;" : "=r"(r) : "f"(x));
    return r;
}
__device__ __forceinline__ float tf32f(float x) { return __uint_as_float(tf32b(x)); }
__device__ __forceinline__ void cpa16(uint32_t saddr, const void* g) {
    asm volatile("cp.async.cg.shared.global [%0], [%1], 16;" :: "r"(saddr), "l"(g));
}
__device__ __forceinline__ void mma8(float* d, const uint32_t* a, uint32_t b0, uint32_t b1) {
    asm volatile(
        "mma.sync.aligned.m16n8k8.row.col.f32.tf32.tf32.f32 "
        "{%0,%1,%2,%3}, {%4,%5,%6,%7}, {%8,%9}, {%0,%1,%2,%3};"
        : "+f"(d[0]), "+f"(d[1]), "+f"(d[2]), "+f"(d[3])
        : "r"(a[0]), "r"(a[1]), "r"(a[2]), "r"(a[3]), "r"(b0), "r"(b1));
}

// =================== tf32 round-copy ===================
__global__ __launch_bounds__(256) void round_copy(const float* __restrict__ src,
                                                  float* __restrict__ dst, int n4)
{
    int i = blockIdx.x * 256 + threadIdx.x;
    if (i < n4) {
        float4 v = ((const float4*)src)[i];
        v.x = tf32f(v.x); v.y = tf32f(v.y); v.z = tf32f(v.z); v.w = tf32f(v.w);
        ((float4*)dst)[i] = v;
    }
}

// =================== mma.sync tf32 GEMM ===================
// R8 operand layout (A[M,K] natural, W[K,N] natural), NEW 256x128 CTA tile.
// 8 warps in 4x2: warp tile 64x64 -> 32 LDS per 32 mma per k8 (was 24/16).
#define BK        32
#define NSTG      3
#define A_ROWB    144                 // 36 floats (32 + 4 pad)
#define B_ROWB    544                 // 136 floats (128 + 8 pad)
#define A_BYTES   (256 * A_ROWB)      // 36864
#define B_BYTES   (BK * B_ROWB)       // 17408
#define STG_BYTES (A_BYTES + B_BYTES) // 54272
#define NT        (GK / BK)           // 64

__device__ __forceinline__ void load_stage(uint32_t sb, const float* __restrict__ A,
                                           const float* __restrict__ W,
                                           int m0, int n0, int kt, int tid) {
    uint32_t st = sb + (uint32_t)(kt % NSTG) * STG_BYTES;
    const int k0 = kt * BK;
#pragma unroll
    for (int i = 0; i < 8; i++) {
        int id = tid + i * 256;            // A: 256 rows x 8 chunks
        int row = id >> 3, seg = id & 7;
        cpa16(st + row * A_ROWB + seg * 16,
              A + (size_t)(m0 + row) * GK + k0 + seg * 4);
    }
#pragma unroll
    for (int i = 0; i < 4; i++) {
        int id = tid + i * 256;            // B: 32 k-rows x 32 chunks
        int kr = id >> 5, seg = id & 31;
        cpa16(st + A_BYTES + kr * B_ROWB + seg * 16,
              W + (size_t)(k0 + kr) * DIM + n0 + seg * 4);
    }
}

__global__ __launch_bounds__(256) void gemm_mma(const float* __restrict__ A,
                                                const float* __restrict__ Wr,
                                                const float* __restrict__ b0p,
                                                const float* __restrict__ b1p,
                                                const float* __restrict__ b2p,
                                                float* __restrict__ C0,
                                                float* __restrict__ C1,
                                                float* __restrict__ C2)
{
    extern __shared__ __align__(16) char smem[];
    const uint32_t sb = smem_u32(smem);
    const int z = blockIdx.z;
    const float* W    = Wr + (size_t)z * DIM * DIM;
    const float* bias = (z == 0) ? b0p : (z == 1) ? b1p : b2p;
    float* C          = (z == 0) ? C0  : (z == 1) ? C1  : C2;

    const int tid  = threadIdx.x;
    const int lane = tid & 31;
    const int wid  = tid >> 5;
    const int wm   = (wid >> 1) * 64;   // 0,64,128,192
    const int wn   = (wid & 1) * 64;    // 0,64
    const int n0   = blockIdx.x * 128;
    const int m0   = blockIdx.y * 256;

    const int gq = lane >> 2;
    const int tg = lane & 3;

    float acc[4][8][4];
#pragma unroll
    for (int mi = 0; mi < 4; mi++)
#pragma unroll
        for (int ni = 0; ni < 8; ni++)
#pragma unroll
            for (int r = 0; r < 4; r++) acc[mi][ni][r] = 0.f;

#pragma unroll
    for (int kt = 0; kt < NSTG; kt++) {
        load_stage(sb, A, W, m0, n0, kt, tid);
        asm volatile("cp.async.commit_group;" ::: "memory");
    }

    for (int kt = 0; kt < NT; kt++) {
        asm volatile("cp.async.wait_group %0;" :: "n"(NSTG - 1) : "memory");
        __syncthreads();

        const float* smf = (const float*)(smem + (kt % NSTG) * STG_BYTES);
        const float* bsf = (const float*)(smem + (kt % NSTG) * STG_BYTES + A_BYTES);

#pragma unroll
        for (int ks = 0; ks < BK; ks += 8) {
            uint32_t afr[4][4];
#pragma unroll
            for (int mi = 0; mi < 4; mi++) {
                int r0 = wm + mi * 16 + gq;
                int c0 = ks + tg;
                afr[mi][0] = __float_as_uint(smf[r0 * 36 + c0]);
                afr[mi][1] = __float_as_uint(smf[(r0 + 8) * 36 + c0]);
                afr[mi][2] = __float_as_uint(smf[r0 * 36 + c0 + 4]);
                afr[mi][3] = __float_as_uint(smf[(r0 + 8) * 36 + c0 + 4]);
            }
#pragma unroll
            for (int ni = 0; ni < 8; ni++) {
                int nb = wn + ni * 8 + gq;
                uint32_t b0 = __float_as_uint(bsf[(ks + tg) * 136 + nb]);
                uint32_t b1 = __float_as_uint(bsf[(ks + tg + 4) * 136 + nb]);
#pragma unroll
                for (int mi = 0; mi < 4; mi++)
                    mma8(acc[mi][ni], afr[mi], b0, b1);
            }
        }
        __syncthreads();

        if (kt + NSTG < NT)
            load_stage(sb, A, W, m0, n0, kt + NSTG, tid);
        asm volatile("cp.async.commit_group;" ::: "memory");
    }

#pragma unroll
    for (int mi = 0; mi < 4; mi++) {
        int row = m0 + wm + mi * 16 + gq;
#pragma unroll
        for (int ni = 0; ni < 8; ni++) {
            int col = n0 + wn + ni * 8 + 2 * tg;
            float2 bz = *(const float2*)(bias + col);
            float2 v0, v1;
            v0.x = acc[mi][ni][0] + bz.x; v0.y = acc[mi][ni][1] + bz.y;
            v1.x = acc[mi][ni][2] + bz.x; v1.y = acc[mi][ni][3] + bz.y;
            *(float2*)(C + (size_t)row * DIM + col)       = v0;
            *(float2*)(C + (size_t)(row + 8) * DIM + col) = v1;
        }
    }
}

// ---------------- RMSNorm + RoPE ----------------
// grid.y==0: Q in-place, rounded (natural order, feeds flash A-frags + Wo GEMM)
// grid.y==1: K -> Kp, rounded + d-permuted (feeds flash B-frags via LDS.64)
__global__ __launch_bounds__(256) void rmsnorm_rope2(float* __restrict__ qb,
                                                     float* __restrict__ kb,
                                                     float* __restrict__ kp,
                                                     const float* __restrict__ gqw,
                                                     const float* __restrict__ gkw,
                                                     const float* __restrict__ freqs)
{
    const int t = blockIdx.x;
    const int isk = blockIdx.y;
    float* row = (isk ? kb : qb) + (size_t)t * DIM;
    const float* g = isk ? gkw : gqw;

    float ss = 0.f;
    for (int i = threadIdx.x; i < DIM; i += 256) {
        float v = row[i];
        ss += v * v;
    }
#pragma unroll
    for (int off = 16; off; off >>= 1) ss += __shfl_xor_sync(0xFFFFFFFFu, ss, off);

    __shared__ float red[8];
    __shared__ float stot;
    if ((threadIdx.x & 31) == 0) red[threadIdx.x >> 5] = ss;
    __syncthreads();
    if (threadIdx.x == 0) {
        float tot = 0.f;
#pragma unroll
        for (int i = 0; i < 8; i++) tot += red[i];
        stot = tot;
    }
    __syncthreads();

    const float scale = rsqrtf(stot * (1.f / DIM) + 1e-6f);
    float* krow = kp + (size_t)t * DIM;

    for (int p = threadIdx.x; p < DIM / 2; p += 256) {
        int e   = 2 * p;
        int pin = p & 63;
        float ang = freqs[(size_t)t * 64 + pin];
        float c, s;
        sincosf(ang, &s, &c);
        float x0 = row[e]     * scale * g[e];
        float x1 = row[e + 1] * scale * g[e + 1];
        float y0 = tf32f(x0 * c - x1 * s);
        float y1 = tf32f(x0 * s + x1 * c);
        if (!isk) {
            row[e]     = y0;
            row[e + 1] = y1;
        } else {
            int base = e & ~7;
            int s0 = e & 7, s1 = s0 + 1;
            krow[base + (((s0 & 3) << 1) | (s0 >> 2))] = y0;
            krow[base + (((s1 & 3) << 1) | (s1 >> 2))] = y1;
        }
    }
}

// ---------------- transpose V -> Vt[h][d][t'] with key-permutation + rounding ----------------
__global__ __launch_bounds__(256) void transpose_v(const float* __restrict__ V,
                                                   float* __restrict__ Vt)
{
    __shared__ float t[32][33];
    const int t0 = blockIdx.x * 32;
    const int d0 = blockIdx.y * 32;
    const int tx = threadIdx.x & 31, ty = threadIdx.x >> 5;
#pragma unroll
    for (int i = 0; i < 4; i++)
        t[ty + 8 * i][tx] = V[(size_t)(t0 + ty + 8 * i) * DIM + d0 + tx];
    __syncthreads();
    const int tperm = (tx & ~7) + ((tx & 7) >> 1) + ((tx & 1) << 2);
#pragma unroll
    for (int i = 0; i < 4; i++)
        Vt[(size_t)(d0 + ty + 8 * i) * T_SEQ + t0 + tx] = tf32f(t[tperm][ty + 8 * i]);
}

// ---------------- causal flash attention via mma.sync tf32 (R8 design) ----------------
#define FA_QT  128
#define FA_KT  64
#define Q_LD   132
#define K_LD   136
#define V_LDW  72
#define SM_Q   0
#define SM_KT  (FA_QT * Q_LD)
#define K_BUF  (FA_KT * K_LD)
#define SM_V   (SM_KT + 2 * K_BUF)
#define V_BUF  (HD * V_LDW)
#define FA_SM_FLOATS (SM_V + 2 * V_BUF)
#define FA_SM_BYTES  (FA_SM_FLOATS * 4)

__device__ __forceinline__ void fa_load_kv(uint32_t sb, const float* __restrict__ Kp,
                                           const float* __restrict__ Vt,
                                           int h, int j, int buf, int tid) {
    const int k0 = j * FA_KT;
    uint32_t kbb = sb + (uint32_t)(SM_KT + buf * K_BUF) * 4;
    uint32_t vbb = sb + (uint32_t)(SM_V + buf * V_BUF) * 4;
#pragma unroll
    for (int i = 0; i < 8; i++) {
        int id = tid + i * 256;
        int key = id >> 5, c = id & 31;
        cpa16(kbb + (uint32_t)(key * K_LD + c * 4) * 4,
              Kp + (size_t)(k0 + key) * DIM + h * HD + c * 4);
    }
#pragma unroll
    for (int i = 0; i < 8; i++) {
        int id = tid + i * 256;
        int d = id >> 4, c = id & 15;
        cpa16(vbb + (uint32_t)(d * V_LDW + c * 4) * 4,
              Vt + (size_t)(h * HD + d) * T_SEQ + k0 + c * 4);
    }
}

__global__ __launch_bounds__(256) void flash_mma(const float* __restrict__ Q,
                                                 const float* __restrict__ Kp_g,
                                                 const float* __restrict__ Vt_g,
                                                 float* __restrict__ O)
{
    extern __shared__ float sm[];
    const uint32_t sb = smem_u32(sm);
    const int qt = gridDim.x - 1 - blockIdx.x;
    const int h  = blockIdx.y;
    const int q0 = qt * FA_QT;
    const int tid  = threadIdx.x;
    const int lane = tid & 31, wid = tid >> 5;
    const int gq = lane >> 2, tg = lane & 3;
    const int wrow = wid * 16;
    const int nkt = 2 * qt + 2;
    const float scale = 0.08838834764831845f;

    for (int idx = tid; idx < FA_QT * 32; idx += 256) {
        int r = idx >> 5, c4 = (idx & 31) * 4;
        float4 v = *(const float4*)(Q + (size_t)(q0 + r) * DIM + h * HD + c4);
        float* dst = sm + SM_Q + r * Q_LD + c4;
        dst[0] = v.x; dst[1] = v.y; dst[2] = v.z; dst[3] = v.w;
    }

    fa_load_kv(sb, Kp_g, Vt_g, h, 0, 0, tid);
    asm volatile("cp.async.commit_group;" ::: "memory");
    __syncthreads();

    const float* Qp  = sm + SM_Q + (wrow + gq) * Q_LD;
    const float* Qp8 = Qp + 8 * Q_LD;
    uint32_t qfr[16][4];
#pragma unroll
    for (int ks = 0; ks < 16; ks++) {
        qfr[ks][0] = __float_as_uint(Qp [ks * 8 + tg]);
        qfr[ks][1] = __float_as_uint(Qp8[ks * 8 + tg]);
        qfr[ks][2] = __float_as_uint(Qp [ks * 8 + tg + 4]);
        qfr[ks][3] = __float_as_uint(Qp8[ks * 8 + tg + 4]);
    }

    float oacc[16][4];
#pragma unroll
    for (int nt = 0; nt < 16; nt++)
#pragma unroll
        for (int r = 0; r < 4; r++) oacc[nt][r] = 0.f;

    float m0 = -1e30f, m1 = -1e30f, l0 = 0.f, l1 = 0.f;
    const int r0 = q0 + wrow + gq, r1 = r0 + 8;

    for (int j = 0; j < nkt; j++) {
        if (j + 1 < nkt)
            fa_load_kv(sb, Kp_g, Vt_g, h, j + 1, (j + 1) & 1, tid);
        asm volatile("cp.async.commit_group;" ::: "memory");
        asm volatile("cp.async.wait_group 1;" ::: "memory");
        __syncthreads();

        const int buf = j & 1;
        const int k0 = j * FA_KT;
        const float* Kpb = sm + SM_KT + buf * K_BUF;
        const float* Vpb = sm + SM_V + buf * V_BUF;

        float sacc[8][4];
#pragma unroll
        for (int nt = 0; nt < 8; nt++)
#pragma unroll
            for (int r = 0; r < 4; r++) sacc[nt][r] = 0.f;

#pragma unroll
        for (int ks = 0; ks < 16; ks++) {
#pragma unroll
            for (int nt = 0; nt < 8; nt++) {
                float2 kb = *(const float2*)(Kpb + (nt * 8 + gq) * K_LD + ks * 8 + 2 * tg);
                mma8(sacc[nt], qfr[ks], __float_as_uint(kb.x), __float_as_uint(kb.y));
            }
        }

        const bool diag = (k0 + FA_KT - 1 > q0);
        float mx0 = -1e30f, mx1 = -1e30f;
#pragma unroll
        for (int nt = 0; nt < 8; nt++) {
            int c0 = k0 + nt * 8 + 2 * tg;
            float s0 = sacc[nt][0] * scale, s1 = sacc[nt][1] * scale;
            float s2 = sacc[nt][2] * scale, s3 = sacc[nt][3] * scale;
            if (diag) {
                if (c0     > r0) s0 = -1e30f;
                if (c0 + 1 > r0) s1 = -1e30f;
                if (c0     > r1) s2 = -1e30f;
                if (c0 + 1 > r1) s3 = -1e30f;
            }
            mx0 = fmaxf(mx0, fmaxf(s0, s1));
            mx1 = fmaxf(mx1, fmaxf(s2, s3));
            sacc[nt][0] = s0; sacc[nt][1] = s1; sacc[nt][2] = s2; sacc[nt][3] = s3;
        }
        mx0 = fmaxf(mx0, __shfl_xor_sync(0xFFFFFFFFu, mx0, 1));
        mx0 = fmaxf(mx0, __shfl_xor_sync(0xFFFFFFFFu, mx0, 2));
        mx1 = fmaxf(mx1, __shfl_xor_sync(0xFFFFFFFFu, mx1, 1));
        mx1 = fmaxf(mx1, __shfl_xor_sync(0xFFFFFFFFu, mx1, 2));

        const float mn0 = fmaxf(m0, mx0), mn1 = fmaxf(m1, mx1);
        const float f0 = __expf(m0 - mn0), f1 = __expf(m1 - mn1);
        m0 = mn0; m1 = mn1;

        float rs0 = 0.f, rs1 = 0.f;
#pragma unroll
        for (int nt = 0; nt < 8; nt++) {
            float e0 = __expf(sacc[nt][0] - mn0);
            float e1 = __expf(sacc[nt][1] - mn0);
            float e2 = __expf(sacc[nt][2] - mn1);
            float e3 = __expf(sacc[nt][3] - mn1);
            rs0 += e0 + e1; rs1 += e2 + e3;
            sacc[nt][0] = __uint_as_float(tf32b(e0));
            sacc[nt][1] = __uint_as_float(tf32b(e1));
            sacc[nt][2] = __uint_as_float(tf32b(e2));
            sacc[nt][3] = __uint_as_float(tf32b(e3));
        }
        rs0 += __shfl_xor_sync(0xFFFFFFFFu, rs0, 1);
        rs0 += __shfl_xor_sync(0xFFFFFFFFu, rs0, 2);
        rs1 += __shfl_xor_sync(0xFFFFFFFFu, rs1, 1);
        rs1 += __shfl_xor_sync(0xFFFFFFFFu, rs1, 2);
        l0 = l0 * f0 + rs0;
        l1 = l1 * f1 + rs1;

#pragma unroll
        for (int nt = 0; nt < 16; nt++) {
            oacc[nt][0] *= f0; oacc[nt][1] *= f0;
            oacc[nt][2] *= f1; oacc[nt][3] *= f1;
        }

        const int src0 = (lane & 28) | (tg >> 1);
        const int src2 = src0 + 2;
#pragma unroll
        for (int s = 0; s < 8; s++) {
            float w0 = __shfl_sync(0xFFFFFFFFu, sacc[s][0], src0);
            float w1 = __shfl_sync(0xFFFFFFFFu, sacc[s][1], src0);
            float w2 = __shfl_sync(0xFFFFFFFFu, sacc[s][2], src0);
            float w3 = __shfl_sync(0xFFFFFFFFu, sacc[s][3], src0);
            float w4 = __shfl_sync(0xFFFFFFFFu, sacc[s][0], src2);
            float w5 = __shfl_sync(0xFFFFFFFFu, sacc[s][1], src2);
            float w6 = __shfl_sync(0xFFFFFFFFu, sacc[s][2], src2);
            float w7 = __shfl_sync(0xFFFFFFFFu, sacc[s][3], src2);
            uint32_t af[4];
            af[0] = __float_as_uint((tg & 1) ? w1 : w0);
            af[1] = __float_as_uint((tg & 1) ? w3 : w2);
            af[2] = __float_as_uint((tg & 1) ? w5 : w4);
            af[3] = __float_as_uint((tg & 1) ? w7 : w6);
#pragma unroll
            for (int nt = 0; nt < 16; nt++) {
                float2 vb = *(const float2*)(Vpb + (nt * 8 + gq) * V_LDW + s * 8 + 2 * tg);
                mma8(oacc[nt], af, __float_as_uint(vb.x), __float_as_uint(vb.y));
            }
        }
        __syncthreads();
    }

    // epilogue: natural order, tf32-rounded (feeds Wo GEMM A operand)
    const float inv0 = 1.f / l0, inv1 = 1.f / l1;
#pragma unroll
    for (int nt = 0; nt < 16; nt++) {
        int col = h * HD + nt * 8 + 2 * tg;
        float2 w0, w1;
        w0.x = tf32f(oacc[nt][0] * inv0); w0.y = tf32f(oacc[nt][1] * inv0);
        w1.x = tf32f(oacc[nt][2] * inv1); w1.y = tf32f(oacc[nt][3] * inv1);
        *(float2*)(O + (size_t)r0 * DIM + col) = w0;
        *(float2*)(O + (size_t)r1 * DIM + col) = w1;
    }
}

// ---------------- launch ----------------
extern "C" void kernel_launch(void* const* d_in, const int* in_sizes, int n_in,
                              void* d_out, int out_size)
{
    (void)in_sizes; (void)n_in; (void)out_size;
    const float* x     = (const float*)d_in[0];
    const float* freqs = (const float*)d_in[1];
    const float* Wq    = (const float*)d_in[2];
    const float* bq    = (const float*)d_in[3];
    const float* Wk    = (const float*)d_in[4];
    const float* bk    = (const float*)d_in[5];
    const float* Wv    = (const float*)d_in[6];
    const float* bv    = (const float*)d_in[7];
    const float* Wo    = (const float*)d_in[8];
    const float* bo    = (const float*)d_in[9];
    const float* gq    = (const float*)d_in[10];
    const float* gk    = (const float*)d_in[11];

    float *q, *k, *v, *o, *kp, *vt, *xr, *w;
    cudaGetSymbolAddress((void**)&q,  g_q);
    cudaGetSymbolAddress((void**)&k,  g_k);
    cudaGetSymbolAddress((void**)&v,  g_v);
    cudaGetSymbolAddress((void**)&o,  g_o);
    cudaGetSymbolAddress((void**)&kp, g_kp);
    cudaGetSymbolAddress((void**)&vt, g_vt);
    cudaGetSymbolAddress((void**)&xr, g_xr);
    cudaGetSymbolAddress((void**)&w,  g_w);

    const int gsm = NSTG * STG_BYTES;   // 162816
    cudaFuncSetAttribute(gemm_mma, cudaFuncAttributeMaxDynamicSharedMemorySize, gsm);
    cudaFuncSetAttribute(flash_mma, cudaFuncAttributeMaxDynamicSharedMemorySize, FA_SM_BYTES);

    const int W4 = DIM * DIM / 4;
    round_copy<<<(T_SEQ * DIM / 4 + 255) / 256, 256>>>(x, xr, T_SEQ * DIM / 4);
    round_copy<<<(W4 + 255) / 256, 256>>>(Wq, w + 0 * DIM * DIM, W4);
    round_copy<<<(W4 + 255) / 256, 256>>>(Wk, w + 1 * DIM * DIM, W4);
    round_copy<<<(W4 + 255) / 256, 256>>>(Wv, w + 2 * DIM * DIM, W4);
    round_copy<<<(W4 + 255) / 256, 256>>>(Wo, w + 3 * DIM * DIM, W4);

    dim3 qkvgrid(DIM / 128, T_SEQ / 256, 3);   // (16, 16, 3)
    gemm_mma<<<qkvgrid, 256, gsm>>>(xr, w, bq, bk, bv, q, k, v);

    rmsnorm_rope2<<<dim3(T_SEQ, 2), 256>>>(q, k, kp, gq, gk, freqs);

    transpose_v<<<dim3(T_SEQ / 32, DIM / 32), 256>>>(v, vt);

    flash_mma<<<dim3(T_SEQ / FA_QT, NH), 256, FA_SM_BYTES>>>(q, kp, vt, o);

    dim3 ogrid(DIM / 128, T_SEQ / 256, 1);     // (16, 16, 1)
    gemm_mma<<<ogrid, 256, gsm>>>(o, w + 3 * DIM * DIM, bo, bo, bo,
                                  (float*)d_out, (float*)d_out, (float*)d_out);
}

// round 12
// speedup vs baseline: 1.9262x; 1.6655x over previous
#include <cuda_runtime.h>
#include <cuda_fp16.h>
#include <math.h>
#include <stdint.h>

#define T_SEQ 4096
#define DIM   2048
#define NH    16
#define HD    128
#define GK    2048

// ---------------- scratch (no allocations allowed) ----------------
__device__ float  g_q[T_SEQ * DIM];        // fp32 GEMM outputs
__device__ float  g_k[T_SEQ * DIM];
__device__ float  g_v[T_SEQ * DIM];
__device__ __half g_xh[T_SEQ * DIM];       // x fp16, A-perm
__device__ __half g_wh[4 * DIM * DIM];     // weights fp16, chunk layout [g][t][n][u]
__device__ __half g_qh[T_SEQ * DIM];       // Q fp16, A-perm
__device__ __half g_kph[T_SEQ * DIM];      // K fp16 [key][d], chunk-perm on d
__device__ __half g_vth[DIM * T_SEQ];      // V fp16 [d][key'], chunk-perm on key
__device__ __half g_oh[T_SEQ * DIM];       // attn out fp16, A-perm

// =================== helpers ===================
__device__ __forceinline__ uint32_t smem_u32(const void* p) {
    uint32_t a;
    asm("{ .reg .u64 t; cvta.to.shared.u64 t, %1; cvt.u32.u64 %0, t; }" : "=r"(a) : "l"(p));
    return a;
}
__device__ __forceinline__ void cpa16(uint32_t saddr, const void* g) {
    asm volatile("cp.async.cg.shared.global [%0], [%1], 16;" :: "r"(saddr), "l"(g));
}
__device__ __forceinline__ void mma16(float* d, const uint32_t* a, uint32_t b0, uint32_t b1) {
    asm volatile(
        "mma.sync.aligned.m16n8k16.row.col.f32.f16.f16.f32 "
        "{%0,%1,%2,%3}, {%4,%5,%6,%7}, {%8,%9}, {%0,%1,%2,%3};"
        : "+f"(d[0]), "+f"(d[1]), "+f"(d[2]), "+f"(d[3])
        : "r"(a[0]), "r"(a[1]), "r"(a[2]), "r"(a[3]), "r"(b0), "r"(b1));
}
__device__ __forceinline__ uint32_t packh2(float lo, float hi) {
    __half2 h = __floats2half2_rn(lo, hi);
    return *reinterpret_cast<uint32_t*>(&h);
}

// =================== prep: x -> fp16 with A-perm ===================
// A-perm within 16-half groups: word w (0..7) -> pos = w<4 ? 2w : 2(w-4)+1
__global__ __launch_bounds__(256) void prep_x(const float* __restrict__ x,
                                              __half* __restrict__ xh)
{
    int wi = blockIdx.x * 256 + threadIdx.x;     // word index (2 halves)
    int row = wi >> 10, p = wi & 1023;
    int g = p >> 3, pw = p & 7;
    int w = (pw & 1) ? (pw >> 1) + 4 : (pw >> 1);
    float2 v = *(const float2*)(x + (size_t)row * DIM + g * 16 + 2 * w);
    reinterpret_cast<__half2*>(xh)[wi] = __floats2half2_rn(v.x, v.y);
}

// =================== prep: W[K,N] -> fp16 chunk layout ===================
// half idx = g*32768 + t*8192 + n*4 + u ; chunk t holds k = 16g + {2t,2t+1,2t+8,2t+9}
__global__ __launch_bounds__(256) void prep_w(const float* __restrict__ W0,
                                              const float* __restrict__ W1,
                                              const float* __restrict__ W2,
                                              const float* __restrict__ W3,
                                              __half* __restrict__ Wp)
{
    int z = blockIdx.z;
    const float* W = (z == 0) ? W0 : (z == 1) ? W1 : (z == 2) ? W2 : W3;
    __half2* D = reinterpret_cast<__half2*>(Wp + (size_t)z * DIM * DIM);
    int wi = blockIdx.x * 256 + threadIdx.x;     // word index
    int g = wi >> 14;
    int t = (wi >> 12) & 3;
    int q = wi & 4095;
    int n = q >> 1, hi = q & 1;
    int k = 16 * g + 2 * t + 8 * hi;
    float a = W[(size_t)k * DIM + n];
    float b = W[(size_t)(k + 1) * DIM + n];
    D[wi] = __floats2half2_rn(a, b);
}

// =================== fp16 mma GEMM: C[M,N] = A@W + bias ===================
// CTA 256x128, BK=64, 3-stage. A smem rows 40 words (A-perm), B rows 264 words (chunk).
#define BKH     64
#define NSTGH   3
#define AW      40
#define BW      264
#define A_WORDS (256 * AW)            // 10240
#define B_WORDS (16 * BW)             // 4224
#define STGW    (A_WORDS + B_WORDS)   // 14464
#define STGB    (STGW * 4)            // 57856
#define NTH     (GK / BKH)            // 32

__device__ __forceinline__ void load_stage_h(uint32_t sb, const __half* __restrict__ A,
                                             const __half* __restrict__ Wp,
                                             int m0, int n0, int kt, int tid) {
    uint32_t st = sb + (uint32_t)(kt % NSTGH) * STGB;
#pragma unroll
    for (int i = 0; i < 8; i++) {
        int id = tid + i * 256;               // A: 256 rows x 8 chunks (64 halves/row)
        int row = id >> 3, c = id & 7;
        cpa16(st + (uint32_t)(row * AW + c * 4) * 4,
              A + (size_t)(m0 + row) * GK + kt * BKH + c * 8);
    }
#pragma unroll
    for (int i = 0; i < 4; i++) {
        int id = tid + i * 256;               // B: 16 rows x 64 chunks (512 halves/row)
        int row = id >> 6, c = id & 63;
        cpa16(st + (uint32_t)(A_WORDS + row * BW + c * 4) * 4,
              Wp + (size_t)(kt * 16 + row) * 8192 + (size_t)n0 * 4 + c * 8);
    }
}

__global__ __launch_bounds__(256) void gemm_h(const __half* __restrict__ A,
                                              const __half* __restrict__ Wr,
                                              const float* __restrict__ b0p,
                                              const float* __restrict__ b1p,
                                              const float* __restrict__ b2p,
                                              float* __restrict__ C0,
                                              float* __restrict__ C1,
                                              float* __restrict__ C2)
{
    extern __shared__ __align__(16) char smem[];
    const uint32_t sb = smem_u32(smem);
    const int z = blockIdx.z;
    const __half* Wp  = Wr + (size_t)z * DIM * DIM;
    const float* bias = (z == 0) ? b0p : (z == 1) ? b1p : b2p;
    float* C          = (z == 0) ? C0  : (z == 1) ? C1  : C2;

    const int tid  = threadIdx.x;
    const int lane = tid & 31;
    const int wid  = tid >> 5;
    const int wm   = (wid >> 1) * 64;
    const int wn   = (wid & 1) * 64;
    const int n0   = blockIdx.x * 128;
    const int m0   = blockIdx.y * 256;
    const int gq   = lane >> 2;
    const int tg   = lane & 3;

    float acc[4][8][4];
#pragma unroll
    for (int mi = 0; mi < 4; mi++)
#pragma unroll
        for (int ni = 0; ni < 8; ni++)
#pragma unroll
            for (int r = 0; r < 4; r++) acc[mi][ni][r] = 0.f;

#pragma unroll
    for (int kt = 0; kt < NSTGH; kt++) {
        load_stage_h(sb, A, Wp, m0, n0, kt, tid);
        asm volatile("cp.async.commit_group;" ::: "memory");
    }

    for (int kt = 0; kt < NTH; kt++) {
        asm volatile("cp.async.wait_group %0;" :: "n"(NSTGH - 1) : "memory");
        __syncthreads();

        const uint32_t* smw = (const uint32_t*)(smem + (kt % NSTGH) * STGB);
        const uint32_t* smb = smw + A_WORDS;

#pragma unroll
        for (int s = 0; s < 4; s++) {
            uint32_t afr[4][4];
#pragma unroll
            for (int mi = 0; mi < 4; mi++) {
                int r0 = wm + mi * 16 + gq;
                uint2 t0 = *(const uint2*)(smw + r0 * AW + s * 8 + 2 * tg);
                uint2 t1 = *(const uint2*)(smw + (r0 + 8) * AW + s * 8 + 2 * tg);
                afr[mi][0] = t0.x; afr[mi][1] = t1.x;
                afr[mi][2] = t0.y; afr[mi][3] = t1.y;
            }
#pragma unroll
            for (int ni = 0; ni < 8; ni++) {
                int nb = wn + ni * 8 + gq;
                uint2 bb = *(const uint2*)(smb + (s * 4 + tg) * BW + 2 * nb);
#pragma unroll
                for (int mi = 0; mi < 4; mi++)
                    mma16(acc[mi][ni], afr[mi], bb.x, bb.y);
            }
        }
        __syncthreads();

        if (kt + NSTGH < NTH)
            load_stage_h(sb, A, Wp, m0, n0, kt + NSTGH, tid);
        asm volatile("cp.async.commit_group;" ::: "memory");
    }

#pragma unroll
    for (int mi = 0; mi < 4; mi++) {
        int row = m0 + wm + mi * 16 + gq;
#pragma unroll
        for (int ni = 0; ni < 8; ni++) {
            int col = n0 + wn + ni * 8 + 2 * tg;
            float2 bz = *(const float2*)(bias + col);
            float2 v0, v1;
            v0.x = acc[mi][ni][0] + bz.x; v0.y = acc[mi][ni][1] + bz.y;
            v1.x = acc[mi][ni][2] + bz.x; v1.y = acc[mi][ni][3] + bz.y;
            *(float2*)(C + (size_t)row * DIM + col)       = v0;
            *(float2*)(C + (size_t)(row + 8) * DIM + col) = v1;
        }
    }
}

// ---------------- RMSNorm + RoPE: fp32 in, fp16 out ----------------
// y==0: Q -> qh (A-perm). y==1: K -> kph (chunk-perm on d).
__global__ __launch_bounds__(256) void rmsnorm_h(const float* __restrict__ qb,
                                                 const float* __restrict__ kb,
                                                 __half* __restrict__ qh,
                                                 __half* __restrict__ kph,
                                                 const float* __restrict__ gqw,
                                                 const float* __restrict__ gkw,
                                                 const float* __restrict__ freqs)
{
    const int t = blockIdx.x;
    const int isk = blockIdx.y;
    const float* row = (isk ? kb : qb) + (size_t)t * DIM;
    const float* g = isk ? gkw : gqw;

    float ss = 0.f;
    for (int i = threadIdx.x; i < DIM; i += 256) {
        float v = row[i];
        ss += v * v;
    }
#pragma unroll
    for (int off = 16; off; off >>= 1) ss += __shfl_xor_sync(0xFFFFFFFFu, ss, off);

    __shared__ float red[8];
    __shared__ float stot;
    if ((threadIdx.x & 31) == 0) red[threadIdx.x >> 5] = ss;
    __syncthreads();
    if (threadIdx.x == 0) {
        float tot = 0.f;
#pragma unroll
        for (int i = 0; i < 8; i++) tot += red[i];
        stot = tot;
    }
    __syncthreads();

    const float scale = rsqrtf(stot * (1.f / DIM) + 1e-6f);
    __half* outq = qh + (size_t)t * DIM;
    __half* outk = kph + (size_t)t * DIM;

    for (int p = threadIdx.x; p < DIM / 2; p += 256) {
        int e   = 2 * p;
        int pin = p & 63;
        float ang = freqs[(size_t)t * 64 + pin];
        float c, s;
        sincosf(ang, &s, &c);
        float x0 = row[e]     * scale * g[e];
        float x1 = row[e + 1] * scale * g[e + 1];
        float y0 = x0 * c - x1 * s;
        float y1 = x0 * s + x1 * c;
        if (!isk) {
            int pw = (e >> 1) & 7;
            int pos = (pw < 4) ? 2 * pw : 2 * pw - 7;
            int idx = (e & ~15) + pos * 2;
            *reinterpret_cast<__half2*>(outq + idx) = __floats2half2_rn(y0, y1);
        } else {
            int idx = (e & ~15) + ((e >> 1) & 3) * 4 + 2 * ((e >> 3) & 1);
            *reinterpret_cast<__half2*>(outk + idx) = __floats2half2_rn(y0, y1);
        }
    }
}

// ---------------- transpose V -> Vt[d][key'] fp16 with chunk-perm on key ----------------
__global__ __launch_bounds__(256) void transpose_vh(const float* __restrict__ V,
                                                    __half* __restrict__ Vt)
{
    __shared__ float tl[32][33];
    const int t0 = blockIdx.x * 32;
    const int d0 = blockIdx.y * 32;
    const int tx = threadIdx.x & 31, ty = threadIdx.x >> 5;
#pragma unroll
    for (int i = 0; i < 4; i++)
        tl[ty + 8 * i][tx] = V[(size_t)(t0 + ty + 8 * i) * DIM + d0 + tx];
    __syncthreads();
    const int tp = (tx & ~15) + ((tx >> 1) & 3) * 4 + 2 * ((tx >> 3) & 1) + (tx & 1);
#pragma unroll
    for (int i = 0; i < 4; i++)
        Vt[(size_t)(d0 + ty + 8 * i) * T_SEQ + t0 + tp] = __float2half_rn(tl[tx][ty + 8 * i]);
}

// ---------------- causal flash attention via fp16 mma ----------------
#define QW   72
#define KW   72
#define VW   40
#define SMK  (128 * QW)               // 9216 words
#define KBUF (64 * KW)                // 4608
#define SMV  (SMK + 2 * KBUF)         // 18432
#define VBUF (128 * VW)               // 5120
#define FAW  (SMV + 2 * VBUF)         // 28672 words
#define FAB  (FAW * 4)                // 114688 bytes

__device__ __forceinline__ void fa_load_h(uint32_t sb, const __half* __restrict__ Kp,
                                          const __half* __restrict__ Vt,
                                          int h, int j, int buf, int tid) {
    const int k0 = j * 64;
    uint32_t kb = sb + (uint32_t)(SMK + buf * KBUF) * 4;
    uint32_t vb = sb + (uint32_t)(SMV + buf * VBUF) * 4;
#pragma unroll
    for (int i = 0; i < 4; i++) {
        int id = tid + i * 256;               // K: 64 keys x 16 chunks (128 halves/key)
        int key = id >> 4, c = id & 15;
        cpa16(kb + (uint32_t)(key * KW + c * 4) * 4,
              Kp + (size_t)(k0 + key) * DIM + h * HD + c * 8);
    }
#pragma unroll
    for (int i = 0; i < 4; i++) {
        int id = tid + i * 256;               // V: 128 d x 8 chunks (64 halves/d)
        int d = id >> 3, c = id & 7;
        cpa16(vb + (uint32_t)(d * VW + c * 4) * 4,
              Vt + (size_t)(h * HD + d) * T_SEQ + k0 + c * 8);
    }
}

__global__ __launch_bounds__(256) void flash_h(const __half* __restrict__ Q,
                                               const __half* __restrict__ Kp,
                                               const __half* __restrict__ Vt,
                                               __half* __restrict__ O)
{
    extern __shared__ __align__(16) char smraw[];
    const uint32_t sb = smem_u32(smraw);
    const uint32_t* smw = (const uint32_t*)smraw;
    const int qt = gridDim.x - 1 - blockIdx.x;
    const int h  = blockIdx.y;
    const int q0 = qt * 128;
    const int tid  = threadIdx.x;
    const int lane = tid & 31, wid = tid >> 5;
    const int gq = lane >> 2, tg = lane & 3;
    const int wrow = wid * 16;
    const int nkt = 2 * qt + 2;
    const float scale = 0.08838834764831845f;

    // Q tile (cp.async, group 0 together with first KV)
    for (int idx = tid; idx < 2048; idx += 256) {
        int r = idx >> 4, c = idx & 15;
        cpa16(sb + (uint32_t)(r * QW + c * 4) * 4,
              Q + (size_t)(q0 + r) * DIM + h * HD + c * 8);
    }
    fa_load_h(sb, Kp, Vt, h, 0, 0, tid);
    asm volatile("cp.async.commit_group;" ::: "memory");
    asm volatile("cp.async.wait_group 0;" ::: "memory");
    __syncthreads();

    // hoist Q fragments (8 k16-steps x 4 regs)
    uint32_t qfr[8][4];
    {
        const uint32_t* Qp = smw + (wrow + gq) * QW;
#pragma unroll
        for (int s = 0; s < 8; s++) {
            uint2 t0 = *(const uint2*)(Qp + s * 8 + 2 * tg);
            uint2 t1 = *(const uint2*)(Qp + 8 * QW + s * 8 + 2 * tg);
            qfr[s][0] = t0.x; qfr[s][1] = t1.x;
            qfr[s][2] = t0.y; qfr[s][3] = t1.y;
        }
    }

    float oacc[16][4];
#pragma unroll
    for (int nt = 0; nt < 16; nt++)
#pragma unroll
        for (int r = 0; r < 4; r++) oacc[nt][r] = 0.f;

    float m0 = -1e30f, m1 = -1e30f, l0 = 0.f, l1 = 0.f;
    const int r0 = q0 + wrow + gq, r1 = r0 + 8;

    for (int j = 0; j < nkt; j++) {
        if (j + 1 < nkt)
            fa_load_h(sb, Kp, Vt, h, j + 1, (j + 1) & 1, tid);
        asm volatile("cp.async.commit_group;" ::: "memory");
        asm volatile("cp.async.wait_group 1;" ::: "memory");
        __syncthreads();

        const int buf = j & 1;
        const int k0 = j * 64;
        const uint32_t* Kw = smw + SMK + buf * KBUF;
        const uint32_t* Vw = smw + SMV + buf * VBUF;

        float sacc[8][4];
#pragma unroll
        for (int nt = 0; nt < 8; nt++)
#pragma unroll
            for (int r = 0; r < 4; r++) sacc[nt][r] = 0.f;

#pragma unroll
        for (int s = 0; s < 8; s++) {
#pragma unroll
            for (int nt = 0; nt < 8; nt++) {
                uint2 kb2 = *(const uint2*)(Kw + (nt * 8 + gq) * KW + s * 8 + 2 * tg);
                mma16(sacc[nt], qfr[s], kb2.x, kb2.y);
            }
        }

        const bool diag = (k0 + 63 > q0);
        float mx0 = -1e30f, mx1 = -1e30f;
#pragma unroll
        for (int nt = 0; nt < 8; nt++) {
            int c0 = k0 + nt * 8 + 2 * tg;
            float s0 = sacc[nt][0] * scale, s1 = sacc[nt][1] * scale;
            float s2 = sacc[nt][2] * scale, s3 = sacc[nt][3] * scale;
            if (diag) {
                if (c0     > r0) s0 = -1e30f;
                if (c0 + 1 > r0) s1 = -1e30f;
                if (c0     > r1) s2 = -1e30f;
                if (c0 + 1 > r1) s3 = -1e30f;
            }
            mx0 = fmaxf(mx0, fmaxf(s0, s1));
            mx1 = fmaxf(mx1, fmaxf(s2, s3));
            sacc[nt][0] = s0; sacc[nt][1] = s1; sacc[nt][2] = s2; sacc[nt][3] = s3;
        }
        mx0 = fmaxf(mx0, __shfl_xor_sync(0xFFFFFFFFu, mx0, 1));
        mx0 = fmaxf(mx0, __shfl_xor_sync(0xFFFFFFFFu, mx0, 2));
        mx1 = fmaxf(mx1, __shfl_xor_sync(0xFFFFFFFFu, mx1, 1));
        mx1 = fmaxf(mx1, __shfl_xor_sync(0xFFFFFFFFu, mx1, 2));

        const float mn0 = fmaxf(m0, mx0), mn1 = fmaxf(m1, mx1);
        const float f0 = __expf(m0 - mn0), f1 = __expf(m1 - mn1);
        m0 = mn0; m1 = mn1;

        float rs0 = 0.f, rs1 = 0.f;
#pragma unroll
        for (int nt = 0; nt < 8; nt++) {
            float e0 = __expf(sacc[nt][0] - mn0);
            float e1 = __expf(sacc[nt][1] - mn0);
            float e2 = __expf(sacc[nt][2] - mn1);
            float e3 = __expf(sacc[nt][3] - mn1);
            rs0 += e0 + e1; rs1 += e2 + e3;
            sacc[nt][0] = e0; sacc[nt][1] = e1;
            sacc[nt][2] = e2; sacc[nt][3] = e3;
        }
        rs0 += __shfl_xor_sync(0xFFFFFFFFu, rs0, 1);
        rs0 += __shfl_xor_sync(0xFFFFFFFFu, rs0, 2);
        rs1 += __shfl_xor_sync(0xFFFFFFFFu, rs1, 1);
        rs1 += __shfl_xor_sync(0xFFFFFFFFu, rs1, 2);
        l0 = l0 * f0 + rs0;
        l1 = l1 * f1 + rs1;

#pragma unroll
        for (int nt = 0; nt < 16; nt++) {
            oacc[nt][0] *= f0; oacc[nt][1] *= f0;
            oacc[nt][2] *= f1; oacc[nt][3] *= f1;
        }

        // P accumulator layout == fp16 A-fragment layout: just pack, no shuffles.
#pragma unroll
        for (int s = 0; s < 4; s++) {
            uint32_t pa[4];
            pa[0] = packh2(sacc[2 * s][0],     sacc[2 * s][1]);
            pa[1] = packh2(sacc[2 * s][2],     sacc[2 * s][3]);
            pa[2] = packh2(sacc[2 * s + 1][0], sacc[2 * s + 1][1]);
            pa[3] = packh2(sacc[2 * s + 1][2], sacc[2 * s + 1][3]);
#pragma unroll
            for (int nt = 0; nt < 16; nt++) {
                uint2 vb2 = *(const uint2*)(Vw + (nt * 8 + gq) * VW + s * 8 + 2 * tg);
                mma16(oacc[nt], pa, vb2.x, vb2.y);
            }
        }
        __syncthreads();
    }

    // epilogue: fp16 with A-perm (feeds Wo GEMM A operand)
    const float inv0 = 1.f / l0, inv1 = 1.f / l1;
#pragma unroll
    for (int nt = 0; nt < 16; nt++) {
        int wg = 64 * h + nt * 4 + tg;          // global word idx of col pair
        int gg = wg >> 3, pw = wg & 7;
        int pos = (pw < 4) ? 2 * pw : 2 * pw - 7;
        int idx = gg * 16 + pos * 2;
        *reinterpret_cast<__half2*>(O + (size_t)r0 * DIM + idx) =
            __floats2half2_rn(oacc[nt][0] * inv0, oacc[nt][1] * inv0);
        *reinterpret_cast<__half2*>(O + (size_t)r1 * DIM + idx) =
            __floats2half2_rn(oacc[nt][2] * inv1, oacc[nt][3] * inv1);
    }
}

// ---------------- launch ----------------
extern "C" void kernel_launch(void* const* d_in, const int* in_sizes, int n_in,
                              void* d_out, int out_size)
{
    (void)in_sizes; (void)n_in; (void)out_size;
    const float* x     = (const float*)d_in[0];
    const float* freqs = (const float*)d_in[1];
    const float* Wq    = (const float*)d_in[2];
    const float* bq    = (const float*)d_in[3];
    const float* Wk    = (const float*)d_in[4];
    const float* bk    = (const float*)d_in[5];
    const float* Wv    = (const float*)d_in[6];
    const float* bv    = (const float*)d_in[7];
    const float* Wo    = (const float*)d_in[8];
    const float* bo    = (const float*)d_in[9];
    const float* gq    = (const float*)d_in[10];
    const float* gk    = (const float*)d_in[11];

    float *q, *k, *v;
    __half *xh, *wh, *qh, *kph, *vth, *oh;
    cudaGetSymbolAddress((void**)&q,   g_q);
    cudaGetSymbolAddress((void**)&k,   g_k);
    cudaGetSymbolAddress((void**)&v,   g_v);
    cudaGetSymbolAddress((void**)&xh,  g_xh);
    cudaGetSymbolAddress((void**)&wh,  g_wh);
    cudaGetSymbolAddress((void**)&qh,  g_qh);
    cudaGetSymbolAddress((void**)&kph, g_kph);
    cudaGetSymbolAddress((void**)&vth, g_vth);
    cudaGetSymbolAddress((void**)&oh,  g_oh);

    const int gsm = NSTGH * STGB;   // 173568
    cudaFuncSetAttribute(gemm_h, cudaFuncAttributeMaxDynamicSharedMemorySize, gsm);
    cudaFuncSetAttribute(flash_h, cudaFuncAttributeMaxDynamicSharedMemorySize, FAB);

    prep_x<<<T_SEQ * DIM / 2 / 256, 256>>>(x, xh);
    prep_w<<<dim3(DIM * DIM / 2 / 256, 1, 4), 256>>>(Wq, Wk, Wv, Wo, wh);

    dim3 qkvgrid(DIM / 128, T_SEQ / 256, 3);   // (16, 16, 3)
    gemm_h<<<qkvgrid, 256, gsm>>>(xh, wh, bq, bk, bv, q, k, v);

    rmsnorm_h<<<dim3(T_SEQ, 2), 256>>>(q, k, qh, kph, gq, gk, freqs);

    transpose_vh<<<dim3(T_SEQ / 32, DIM / 32), 256>>>(v, vth);

    flash_h<<<dim3(T_SEQ / 128, NH), 256, FAB>>>(qh, kph, vth, oh);

    dim3 ogrid(DIM / 128, T_SEQ / 256, 1);     // (16, 16, 1)
    gemm_h<<<ogrid, 256, gsm>>>(oh, wh + (size_t)3 * DIM * DIM, bo, bo, bo,
                                (float*)d_out, (float*)d_out, (float*)d_out);
}

// round 14
// speedup vs baseline: 1.9929x; 1.0347x over previous
#include <cuda_runtime.h>
#include <cuda_fp16.h>
#include <math.h>
#include <stdint.h>

#define T_SEQ 4096
#define DIM   2048
#define NH    16
#define HD    128
#define GK    2048

// ---------------- scratch (no allocations allowed) ----------------
__device__ float  g_q[T_SEQ * DIM];        // fp32 GEMM outputs
__device__ float  g_k[T_SEQ * DIM];
__device__ float  g_v[T_SEQ * DIM];
__device__ float2 g_cs[T_SEQ * 64];        // rope cos/sin table
__device__ __half g_xh[T_SEQ * DIM];       // x fp16, A-perm
__device__ __half g_wh[4 * DIM * DIM];     // weights fp16, chunk layout [g][t][n][u]
__device__ __half g_qh[T_SEQ * DIM];       // Q fp16 (pre-scaled by 1/sqrt(HD)), A-perm
__device__ __half g_kph[T_SEQ * DIM];      // K fp16 [key][d], chunk-perm on d
__device__ __half g_vth[DIM * T_SEQ];      // V fp16 [d][key'], chunk-perm on key
__device__ __half g_oh[T_SEQ * DIM];       // attn out fp16, A-perm

// =================== helpers ===================
__device__ __forceinline__ uint32_t smem_u32(const void* p) {
    uint32_t a;
    asm("{ .reg .u64 t; cvta.to.shared.u64 t, %1; cvt.u32.u64 %0, t; }" : "=r"(a) : "l"(p));
    return a;
}
__device__ __forceinline__ void cpa16(uint32_t saddr, const void* g) {
    asm volatile("cp.async.cg.shared.global [%0], [%1], 16;" :: "r"(saddr), "l"(g));
}
__device__ __forceinline__ void mma16(float* d, const uint32_t* a, uint32_t b0, uint32_t b1) {
    asm volatile(
        "mma.sync.aligned.m16n8k16.row.col.f32.f16.f16.f32 "
        "{%0,%1,%2,%3}, {%4,%5,%6,%7}, {%8,%9}, {%0,%1,%2,%3};"
        : "+f"(d[0]), "+f"(d[1]), "+f"(d[2]), "+f"(d[3])
        : "r"(a[0]), "r"(a[1]), "r"(a[2]), "r"(a[3]), "r"(b0), "r"(b1));
}
__device__ __forceinline__ uint32_t packh2(float lo, float hi) {
    __half2 h = __floats2half2_rn(lo, hi);
    return *reinterpret_cast<uint32_t*>(&h);
}

// =================== rope cos/sin table ===================
__global__ __launch_bounds__(256) void rope_tab(const float* __restrict__ freqs,
                                                float2* __restrict__ tab)
{
    int i = blockIdx.x * 256 + threadIdx.x;    // T*64
    float ang = freqs[i];
    float s, c;
    sincosf(ang, &s, &c);
    tab[i] = make_float2(c, s);
}

// =================== prep: x -> fp16 with A-perm ===================
__global__ __launch_bounds__(256) void prep_x(const float* __restrict__ x,
                                              __half* __restrict__ xh)
{
    int wi = blockIdx.x * 256 + threadIdx.x;
    int row = wi >> 10, p = wi & 1023;
    int g = p >> 3, pw = p & 7;
    int w = (pw & 1) ? (pw >> 1) + 4 : (pw >> 1);
    float2 v = *(const float2*)(x + (size_t)row * DIM + g * 16 + 2 * w);
    reinterpret_cast<__half2*>(xh)[wi] = __floats2half2_rn(v.x, v.y);
}

// =================== prep: W[K,N] -> fp16 chunk layout ===================
__global__ __launch_bounds__(256) void prep_w(const float* __restrict__ W0,
                                              const float* __restrict__ W1,
                                              const float* __restrict__ W2,
                                              const float* __restrict__ W3,
                                              __half* __restrict__ Wp)
{
    int z = blockIdx.z;
    const float* W = (z == 0) ? W0 : (z == 1) ? W1 : (z == 2) ? W2 : W3;
    __half2* D = reinterpret_cast<__half2*>(Wp + (size_t)z * DIM * DIM);
    int wi = blockIdx.x * 256 + threadIdx.x;
    int g = wi >> 14;
    int t = (wi >> 12) & 3;
    int q = wi & 4095;
    int n = q >> 1, hi = q & 1;
    int k = 16 * g + 2 * t + 8 * hi;
    float a = W[(size_t)k * DIM + n];
    float b = W[(size_t)(k + 1) * DIM + n];
    D[wi] = __floats2half2_rn(a, b);
}

// =================== fp16 mma GEMM ===================
#define BKH     64
#define NSTGH   3
#define AW      40
#define BW      264
#define A_WORDS (256 * AW)
#define B_WORDS (16 * BW)
#define STGW    (A_WORDS + B_WORDS)
#define STGB    (STGW * 4)
#define NTH     (GK / BKH)

__device__ __forceinline__ void load_stage_h(uint32_t sb, const __half* __restrict__ A,
                                             const __half* __restrict__ Wp,
                                             int m0, int n0, int kt, int tid) {
    uint32_t st = sb + (uint32_t)(kt % NSTGH) * STGB;
#pragma unroll
    for (int i = 0; i < 8; i++) {
        int id = tid + i * 256;
        int row = id >> 3, c = id & 7;
        cpa16(st + (uint32_t)(row * AW + c * 4) * 4,
              A + (size_t)(m0 + row) * GK + kt * BKH + c * 8);
    }
#pragma unroll
    for (int i = 0; i < 4; i++) {
        int id = tid + i * 256;
        int row = id >> 6, c = id & 63;
        cpa16(st + (uint32_t)(A_WORDS + row * BW + c * 4) * 4,
              Wp + (size_t)(kt * 16 + row) * 8192 + (size_t)n0 * 4 + c * 8);
    }
}

__global__ __launch_bounds__(256) void gemm_h(const __half* __restrict__ A,
                                              const __half* __restrict__ Wr,
                                              const float* __restrict__ b0p,
                                              const float* __restrict__ b1p,
                                              const float* __restrict__ b2p,
                                              float* __restrict__ C0,
                                              float* __restrict__ C1,
                                              float* __restrict__ C2)
{
    extern __shared__ __align__(16) char smem[];
    const uint32_t sb = smem_u32(smem);
    const int z = blockIdx.z;
    const __half* Wp  = Wr + (size_t)z * DIM * DIM;
    const float* bias = (z == 0) ? b0p : (z == 1) ? b1p : b2p;
    float* C          = (z == 0) ? C0  : (z == 1) ? C1  : C2;

    const int tid  = threadIdx.x;
    const int lane = tid & 31;
    const int wid  = tid >> 5;
    const int wm   = (wid >> 1) * 64;
    const int wn   = (wid & 1) * 64;
    const int n0   = blockIdx.x * 128;
    const int m0   = blockIdx.y * 256;
    const int gq   = lane >> 2;
    const int tg   = lane & 3;

    float acc[4][8][4];
#pragma unroll
    for (int mi = 0; mi < 4; mi++)
#pragma unroll
        for (int ni = 0; ni < 8; ni++)
#pragma unroll
            for (int r = 0; r < 4; r++) acc[mi][ni][r] = 0.f;

#pragma unroll
    for (int kt = 0; kt < NSTGH; kt++) {
        load_stage_h(sb, A, Wp, m0, n0, kt, tid);
        asm volatile("cp.async.commit_group;" ::: "memory");
    }

    for (int kt = 0; kt < NTH; kt++) {
        asm volatile("cp.async.wait_group %0;" :: "n"(NSTGH - 1) : "memory");
        __syncthreads();

        const uint32_t* smw = (const uint32_t*)(smem + (kt % NSTGH) * STGB);
        const uint32_t* smb = smw + A_WORDS;

#pragma unroll
        for (int s = 0; s < 4; s++) {
            uint32_t afr[4][4];
#pragma unroll
            for (int mi = 0; mi < 4; mi++) {
                int r0 = wm + mi * 16 + gq;
                uint2 t0 = *(const uint2*)(smw + r0 * AW + s * 8 + 2 * tg);
                uint2 t1 = *(const uint2*)(smw + (r0 + 8) * AW + s * 8 + 2 * tg);
                afr[mi][0] = t0.x; afr[mi][1] = t1.x;
                afr[mi][2] = t0.y; afr[mi][3] = t1.y;
            }
#pragma unroll
            for (int ni = 0; ni < 8; ni++) {
                int nb = wn + ni * 8 + gq;
                uint2 bb = *(const uint2*)(smb + (s * 4 + tg) * BW + 2 * nb);
#pragma unroll
                for (int mi = 0; mi < 4; mi++)
                    mma16(acc[mi][ni], afr[mi], bb.x, bb.y);
            }
        }
        __syncthreads();

        if (kt + NSTGH < NTH)
            load_stage_h(sb, A, Wp, m0, n0, kt + NSTGH, tid);
        asm volatile("cp.async.commit_group;" ::: "memory");
    }

#pragma unroll
    for (int mi = 0; mi < 4; mi++) {
        int row = m0 + wm + mi * 16 + gq;
#pragma unroll
        for (int ni = 0; ni < 8; ni++) {
            int col = n0 + wn + ni * 8 + 2 * tg;
            float2 bz = *(const float2*)(bias + col);
            float2 v0, v1;
            v0.x = acc[mi][ni][0] + bz.x; v0.y = acc[mi][ni][1] + bz.y;
            v1.x = acc[mi][ni][2] + bz.x; v1.y = acc[mi][ni][3] + bz.y;
            *(float2*)(C + (size_t)row * DIM + col)       = v0;
            *(float2*)(C + (size_t)(row + 8) * DIM + col) = v1;
        }
    }
}

// ---------------- RMSNorm + RoPE (table-driven): fp32 in, fp16 out ----------------
#define ATT_SCALE 0.08838834764831845f
__global__ __launch_bounds__(256) void rmsnorm_h(const float* __restrict__ qb,
                                                 const float* __restrict__ kb,
                                                 __half* __restrict__ qh,
                                                 __half* __restrict__ kph,
                                                 const float* __restrict__ gqw,
                                                 const float* __restrict__ gkw,
                                                 const float2* __restrict__ tab)
{
    const int t = blockIdx.x;
    const int isk = blockIdx.y;
    const float* row = (isk ? kb : qb) + (size_t)t * DIM;
    const float* g = isk ? gkw : gqw;
    const float2* cs = tab + (size_t)t * 64;

    float ss = 0.f;
    for (int i = threadIdx.x; i < DIM; i += 256) {
        float v = row[i];
        ss += v * v;
    }
#pragma unroll
    for (int off = 16; off; off >>= 1) ss += __shfl_xor_sync(0xFFFFFFFFu, ss, off);

    __shared__ float red[8];
    __shared__ float stot;
    if ((threadIdx.x & 31) == 0) red[threadIdx.x >> 5] = ss;
    __syncthreads();
    if (threadIdx.x == 0) {
        float tot = 0.f;
#pragma unroll
        for (int i = 0; i < 8; i++) tot += red[i];
        stot = tot;
    }
    __syncthreads();

    const float scale = rsqrtf(stot * (1.f / DIM) + 1e-6f);
    __half* outq = qh + (size_t)t * DIM;
    __half* outk = kph + (size_t)t * DIM;

    for (int p = threadIdx.x; p < DIM / 2; p += 256) {
        int e   = 2 * p;
        float2 t2 = cs[p & 63];
        float c = t2.x, s = t2.y;
        float x0 = row[e]     * scale * g[e];
        float x1 = row[e + 1] * scale * g[e + 1];
        float y0 = x0 * c - x1 * s;
        float y1 = x0 * s + x1 * c;
        if (!isk) {
            y0 *= ATT_SCALE;          // fold softmax scale into Q
            y1 *= ATT_SCALE;
            int pw = (e >> 1) & 7;
            int pos = (pw < 4) ? 2 * pw : 2 * pw - 7;
            int idx = (e & ~15) + pos * 2;
            *reinterpret_cast<__half2*>(outq + idx) = __floats2half2_rn(y0, y1);
        } else {
            int idx = (e & ~15) + ((e >> 1) & 3) * 4 + 2 * ((e >> 3) & 1);
            *reinterpret_cast<__half2*>(outk + idx) = __floats2half2_rn(y0, y1);
        }
    }
}

// ---------------- transpose V -> Vt[d][key'] fp16 with chunk-perm on key ----------------
__global__ __launch_bounds__(256) void transpose_vh(const float* __restrict__ V,
                                                    __half* __restrict__ Vt)
{
    __shared__ float tl[32][33];
    const int t0 = blockIdx.x * 32;
    const int d0 = blockIdx.y * 32;
    const int tx = threadIdx.x & 31, ty = threadIdx.x >> 5;
#pragma unroll
    for (int i = 0; i < 4; i++)
        tl[ty + 8 * i][tx] = V[(size_t)(t0 + ty + 8 * i) * DIM + d0 + tx];
    __syncthreads();
    const int tp = (tx & ~15) + ((tx >> 1) & 3) * 4 + 2 * ((tx >> 3) & 1) + (tx & 1);
#pragma unroll
    for (int i = 0; i < 4; i++)
        Vt[(size_t)(d0 + ty + 8 * i) * T_SEQ + t0 + tp] = __float2half_rn(tl[tx][ty + 8 * i]);
}

// ---------------- causal flash attention via fp16 mma ----------------
#define QW   72
#define KW   72
#define VW   40
#define SMK  (128 * QW)
#define KBUF (64 * KW)
#define SMV  (SMK + 2 * KBUF)
#define VBUF (128 * VW)
#define FAW  (SMV + 2 * VBUF)
#define FAB  (FAW * 4)

__device__ __forceinline__ void fa_load_h(uint32_t sb, const __half* __restrict__ Kp,
                                          const __half* __restrict__ Vt,
                                          int h, int j, int buf, int tid) {
    const int k0 = j * 64;
    uint32_t kb = sb + (uint32_t)(SMK + buf * KBUF) * 4;
    uint32_t vb = sb + (uint32_t)(SMV + buf * VBUF) * 4;
#pragma unroll
    for (int i = 0; i < 4; i++) {
        int id = tid + i * 256;
        int key = id >> 4, c = id & 15;
        cpa16(kb + (uint32_t)(key * KW + c * 4) * 4,
              Kp + (size_t)(k0 + key) * DIM + h * HD + c * 8);
    }
#pragma unroll
    for (int i = 0; i < 4; i++) {
        int id = tid + i * 256;
        int d = id >> 3, c = id & 7;
        cpa16(vb + (uint32_t)(d * VW + c * 4) * 4,
              Vt + (size_t)(h * HD + d) * T_SEQ + k0 + c * 8);
    }
}

__global__ __launch_bounds__(256) void flash_h(const __half* __restrict__ Q,
                                               const __half* __restrict__ Kp,
                                               const __half* __restrict__ Vt,
                                               __half* __restrict__ O)
{
    extern __shared__ __align__(16) char smraw[];
    const uint32_t sb = smem_u32(smraw);
    const uint32_t* smw = (const uint32_t*)smraw;
    const int qt = gridDim.x - 1 - blockIdx.x;
    const int h  = blockIdx.y;
    const int q0 = qt * 128;
    const int tid  = threadIdx.x;
    const int lane = tid & 31, wid = tid >> 5;
    const int gq = lane >> 2, tg = lane & 3;
    const int wrow = wid * 16;
    const int nkt = 2 * qt + 2;

    // Q tile + first KV in one async group
    for (int idx = tid; idx < 2048; idx += 256) {
        int r = idx >> 4, c = idx & 15;
        cpa16(sb + (uint32_t)(r * QW + c * 4) * 4,
              Q + (size_t)(q0 + r) * DIM + h * HD + c * 8);
    }
    fa_load_h(sb, Kp, Vt, h, 0, 0, tid);
    asm volatile("cp.async.commit_group;" ::: "memory");
    asm volatile("cp.async.wait_group 0;" ::: "memory");
    __syncthreads();

    uint32_t qfr[8][4];
    {
        const uint32_t* Qp = smw + (wrow + gq) * QW;
#pragma unroll
        for (int s = 0; s < 8; s++) {
            uint2 t0 = *(const uint2*)(Qp + s * 8 + 2 * tg);
            uint2 t1 = *(const uint2*)(Qp + 8 * QW + s * 8 + 2 * tg);
            qfr[s][0] = t0.x; qfr[s][1] = t1.x;
            qfr[s][2] = t0.y; qfr[s][3] = t1.y;
        }
    }

    float oacc[16][4];
#pragma unroll
    for (int nt = 0; nt < 16; nt++)
#pragma unroll
        for (int r = 0; r < 4; r++) oacc[nt][r] = 0.f;

    float m0 = -1e30f, m1 = -1e30f, l0 = 0.f, l1 = 0.f;
    const int r0 = q0 + wrow + gq, r1 = r0 + 8;

    for (int j = 0; j < nkt; j++) {
        // prefetch next tile BEFORE compute (overlaps with this tile's compute)
        if (j + 1 < nkt) {
            fa_load_h(sb, Kp, Vt, h, j + 1, (j + 1) & 1, tid);
            asm volatile("cp.async.commit_group;" ::: "memory");
        }

        const int buf = j & 1;
        const int k0 = j * 64;
        const uint32_t* Kw = smw + SMK + buf * KBUF;
        const uint32_t* Vw = smw + SMV + buf * VBUF;

        float sacc[8][4];
#pragma unroll
        for (int nt = 0; nt < 8; nt++)
#pragma unroll
            for (int r = 0; r < 4; r++) sacc[nt][r] = 0.f;

#pragma unroll
        for (int s = 0; s < 8; s++) {
#pragma unroll
            for (int nt = 0; nt < 8; nt++) {
                uint2 kb2 = *(const uint2*)(Kw + (nt * 8 + gq) * KW + s * 8 + 2 * tg);
                mma16(sacc[nt], qfr[s], kb2.x, kb2.y);
            }
        }

        // scale already folded into Q. Uniform branch on diagonal tile.
        float mx0 = -1e30f, mx1 = -1e30f;
        if (k0 + 63 > q0) {
#pragma unroll
            for (int nt = 0; nt < 8; nt++) {
                int c0 = k0 + nt * 8 + 2 * tg;
                if (c0     > r0) sacc[nt][0] = -1e30f;
                if (c0 + 1 > r0) sacc[nt][1] = -1e30f;
                if (c0     > r1) sacc[nt][2] = -1e30f;
                if (c0 + 1 > r1) sacc[nt][3] = -1e30f;
                mx0 = fmaxf(mx0, fmaxf(sacc[nt][0], sacc[nt][1]));
                mx1 = fmaxf(mx1, fmaxf(sacc[nt][2], sacc[nt][3]));
            }
        } else {
#pragma unroll
            for (int nt = 0; nt < 8; nt++) {
                mx0 = fmaxf(mx0, fmaxf(sacc[nt][0], sacc[nt][1]));
                mx1 = fmaxf(mx1, fmaxf(sacc[nt][2], sacc[nt][3]));
            }
        }
        mx0 = fmaxf(mx0, __shfl_xor_sync(0xFFFFFFFFu, mx0, 1));
        mx0 = fmaxf(mx0, __shfl_xor_sync(0xFFFFFFFFu, mx0, 2));
        mx1 = fmaxf(mx1, __shfl_xor_sync(0xFFFFFFFFu, mx1, 1));
        mx1 = fmaxf(mx1, __shfl_xor_sync(0xFFFFFFFFu, mx1, 2));

        const float mn0 = fmaxf(m0, mx0), mn1 = fmaxf(m1, mx1);
        const float f0 = __expf(m0 - mn0), f1 = __expf(m1 - mn1);
        m0 = mn0; m1 = mn1;

        float rs0 = 0.f, rs1 = 0.f;
#pragma unroll
        for (int nt = 0; nt < 8; nt++) {
            float e0 = __expf(sacc[nt][0] - mn0);
            float e1 = __expf(sacc[nt][1] - mn0);
            float e2 = __expf(sacc[nt][2] - mn1);
            float e3 = __expf(sacc[nt][3] - mn1);
            rs0 += e0 + e1; rs1 += e2 + e3;
            sacc[nt][0] = e0; sacc[nt][1] = e1;
            sacc[nt][2] = e2; sacc[nt][3] = e3;
        }
        rs0 += __shfl_xor_sync(0xFFFFFFFFu, rs0, 1);
        rs0 += __shfl_xor_sync(0xFFFFFFFFu, rs0, 2);
        rs1 += __shfl_xor_sync(0xFFFFFFFFu, rs1, 1);
        rs1 += __shfl_xor_sync(0xFFFFFFFFu, rs1, 2);
        l0 = l0 * f0 + rs0;
        l1 = l1 * f1 + rs1;

#pragma unroll
        for (int nt = 0; nt < 16; nt++) {
            oacc[nt][0] *= f0; oacc[nt][1] *= f0;
            oacc[nt][2] *= f1; oacc[nt][3] *= f1;
        }

#pragma unroll
        for (int s = 0; s < 4; s++) {
            uint32_t pa[4];
            pa[0] = packh2(sacc[2 * s][0],     sacc[2 * s][1]);
            pa[1] = packh2(sacc[2 * s][2],     sacc[2 * s][3]);
            pa[2] = packh2(sacc[2 * s + 1][0], sacc[2 * s + 1][1]);
            pa[3] = packh2(sacc[2 * s + 1][2], sacc[2 * s + 1][3]);
#pragma unroll
            for (int nt = 0; nt < 16; nt++) {
                uint2 vb2 = *(const uint2*)(Vw + (nt * 8 + gq) * VW + s * 8 + 2 * tg);
                mma16(oacc[nt], pa, vb2.x, vb2.y);
            }
        }

        // wait for next tile's loads, then single barrier
        if (j + 1 < nkt)
            asm volatile("cp.async.wait_group 0;" ::: "memory");
        __syncthreads();
    }

    const float inv0 = 1.f / l0, inv1 = 1.f / l1;
#pragma unroll
    for (int nt = 0; nt < 16; nt++) {
        int wg = 64 * h + nt * 4 + tg;
        int gg = wg >> 3, pw = wg & 7;
        int pos = (pw < 4) ? 2 * pw : 2 * pw - 7;
        int idx = gg * 16 + pos * 2;
        *reinterpret_cast<__half2*>(O + (size_t)r0 * DIM + idx) =
            __floats2half2_rn(oacc[nt][0] * inv0, oacc[nt][1] * inv0);
        *reinterpret_cast<__half2*>(O + (size_t)r1 * DIM + idx) =
            __floats2half2_rn(oacc[nt][2] * inv1, oacc[nt][3] * inv1);
    }
}

// ---------------- launch ----------------
extern "C" void kernel_launch(void* const* d_in, const int* in_sizes, int n_in,
                              void* d_out, int out_size)
{
    (void)in_sizes; (void)n_in; (void)out_size;
    const float* x     = (const float*)d_in[0];
    const float* freqs = (const float*)d_in[1];
    const float* Wq    = (const float*)d_in[2];
    const float* bq    = (const float*)d_in[3];
    const float* Wk    = (const float*)d_in[4];
    const float* bk    = (const float*)d_in[5];
    const float* Wv    = (const float*)d_in[6];
    const float* bv    = (const float*)d_in[7];
    const float* Wo    = (const float*)d_in[8];
    const float* bo    = (const float*)d_in[9];
    const float* gq    = (const float*)d_in[10];
    const float* gk    = (const float*)d_in[11];

    float *q, *k, *v;
    float2* cs;
    __half *xh, *wh, *qh, *kph, *vth, *oh;
    cudaGetSymbolAddress((void**)&q,   g_q);
    cudaGetSymbolAddress((void**)&k,   g_k);
    cudaGetSymbolAddress((void**)&v,   g_v);
    cudaGetSymbolAddress((void**)&cs,  g_cs);
    cudaGetSymbolAddress((void**)&xh,  g_xh);
    cudaGetSymbolAddress((void**)&wh,  g_wh);
    cudaGetSymbolAddress((void**)&qh,  g_qh);
    cudaGetSymbolAddress((void**)&kph, g_kph);
    cudaGetSymbolAddress((void**)&vth, g_vth);
    cudaGetSymbolAddress((void**)&oh,  g_oh);

    const int gsm = NSTGH * STGB;
    cudaFuncSetAttribute(gemm_h, cudaFuncAttributeMaxDynamicSharedMemorySize, gsm);
    cudaFuncSetAttribute(flash_h, cudaFuncAttributeMaxDynamicSharedMemorySize, FAB);

    rope_tab<<<T_SEQ * 64 / 256, 256>>>(freqs, cs);
    prep_x<<<T_SEQ * DIM / 2 / 256, 256>>>(x, xh);
    prep_w<<<dim3(DIM * DIM / 2 / 256, 1, 4), 256>>>(Wq, Wk, Wv, Wo, wh);

    dim3 qkvgrid(DIM / 128, T_SEQ / 256, 3);
    gemm_h<<<qkvgrid, 256, gsm>>>(xh, wh, bq, bk, bv, q, k, v);

    rmsnorm_h<<<dim3(T_SEQ, 2), 256>>>(q, k, qh, kph, gq, gk, cs);

    transpose_vh<<<dim3(T_SEQ / 32, DIM / 32), 256>>>(v, vth);

    flash_h<<<dim3(T_SEQ / 128, NH), 256, FAB>>>(qh, kph, vth, oh);

    dim3 ogrid(DIM / 128, T_SEQ / 256, 1);
    gemm_h<<<ogrid, 256, gsm>>>(oh, wh + (size_t)3 * DIM * DIM, bo, bo, bo,
                                (float*)d_out, (float*)d_out, (float*)d_out);
}

// round 15
// speedup vs baseline: 2.1295x; 1.0685x over previous
#include <cuda_runtime.h>
#include <cuda_fp16.h>
#include <math.h>
#include <stdint.h>

#define T_SEQ 4096
#define DIM   2048
#define NH    16
#define HD    128
#define GK    2048

// ---------------- scratch (no allocations allowed) ----------------
__device__ float  g_q[T_SEQ * DIM];        // fp32 GEMM outputs
__device__ float  g_k[T_SEQ * DIM];
__device__ float  g_v[T_SEQ * DIM];
__device__ float2 g_cs[T_SEQ * 64];        // rope cos/sin table
__device__ __half g_xh[T_SEQ * DIM];       // x fp16, A-perm
__device__ __half g_wh[4 * DIM * DIM];     // weights fp16, chunk layout [g][t][n][u]
__device__ __half g_qh[T_SEQ * DIM];       // Q fp16 (pre-scaled by 1/sqrt(HD)), A-perm
__device__ __half g_kph[T_SEQ * DIM];      // K fp16 [key][d], chunk-perm on d
__device__ __half g_vth[DIM * T_SEQ];      // V fp16 [d][key'], chunk-perm on key
__device__ __half g_oh[T_SEQ * DIM];       // attn out fp16, A-perm

// =================== helpers ===================
__device__ __forceinline__ uint32_t smem_u32(const void* p) {
    uint32_t a;
    asm("{ .reg .u64 t; cvta.to.shared.u64 t, %1; cvt.u32.u64 %0, t; }" : "=r"(a) : "l"(p));
    return a;
}
__device__ __forceinline__ void cpa16(uint32_t saddr, const void* g) {
    asm volatile("cp.async.cg.shared.global [%0], [%1], 16;" :: "r"(saddr), "l"(g));
}
__device__ __forceinline__ void mma16(float* d, const uint32_t* a, uint32_t b0, uint32_t b1) {
    asm volatile(
        "mma.sync.aligned.m16n8k16.row.col.f32.f16.f16.f32 "
        "{%0,%1,%2,%3}, {%4,%5,%6,%7}, {%8,%9}, {%0,%1,%2,%3};"
        : "+f"(d[0]), "+f"(d[1]), "+f"(d[2]), "+f"(d[3])
        : "r"(a[0]), "r"(a[1]), "r"(a[2]), "r"(a[3]), "r"(b0), "r"(b1));
}
__device__ __forceinline__ uint32_t packh2(float lo, float hi) {
    __half2 h = __floats2half2_rn(lo, hi);
    return *reinterpret_cast<uint32_t*>(&h);
}

// =================== rope cos/sin table ===================
__global__ __launch_bounds__(256) void rope_tab(const float* __restrict__ freqs,
                                                float2* __restrict__ tab)
{
    int i = blockIdx.x * 256 + threadIdx.x;    // T*64
    float ang = freqs[i];
    float s, c;
    sincosf(ang, &s, &c);
    tab[i] = make_float2(c, s);
}

// =================== prep: x -> fp16 with A-perm ===================
__global__ __launch_bounds__(256) void prep_x(const float* __restrict__ x,
                                              __half* __restrict__ xh)
{
    int wi = blockIdx.x * 256 + threadIdx.x;
    int row = wi >> 10, p = wi & 1023;
    int g = p >> 3, pw = p & 7;
    int w = (pw & 1) ? (pw >> 1) + 4 : (pw >> 1);
    float2 v = *(const float2*)(x + (size_t)row * DIM + g * 16 + 2 * w);
    reinterpret_cast<__half2*>(xh)[wi] = __floats2half2_rn(v.x, v.y);
}

// =================== prep: W[K,N] -> fp16 chunk layout ===================
__global__ __launch_bounds__(256) void prep_w(const float* __restrict__ W0,
                                              const float* __restrict__ W1,
                                              const float* __restrict__ W2,
                                              const float* __restrict__ W3,
                                              __half* __restrict__ Wp)
{
    int z = blockIdx.z;
    const float* W = (z == 0) ? W0 : (z == 1) ? W1 : (z == 2) ? W2 : W3;
    __half2* D = reinterpret_cast<__half2*>(Wp + (size_t)z * DIM * DIM);
    int wi = blockIdx.x * 256 + threadIdx.x;
    int g = wi >> 14;
    int t = (wi >> 12) & 3;
    int q = wi & 4095;
    int n = q >> 1, hi = q & 1;
    int k = 16 * g + 2 * t + 8 * hi;
    float a = W[(size_t)k * DIM + n];
    float b = W[(size_t)(k + 1) * DIM + n];
    D[wi] = __floats2half2_rn(a, b);
}

// =================== fp16 mma GEMM (128x128 CTA tile, 2 CTAs/SM) ===================
#define BKH     64
#define NSTGH   3
#define AW      40
#define BW      264
#define A_WORDS (128 * AW)            // 5120
#define B_WORDS (16 * BW)             // 4224
#define STGW    (A_WORDS + B_WORDS)   // 9344
#define STGB    (STGW * 4)            // 37376
#define NTH     (GK / BKH)            // 32

__device__ __forceinline__ void load_stage_h(uint32_t sb, const __half* __restrict__ A,
                                             const __half* __restrict__ Wp,
                                             int m0, int n0, int kt, int tid) {
    uint32_t st = sb + (uint32_t)(kt % NSTGH) * STGB;
#pragma unroll
    for (int i = 0; i < 4; i++) {
        int id = tid + i * 256;               // A: 128 rows x 8 chunks (64 halves/row)
        int row = id >> 3, c = id & 7;
        cpa16(st + (uint32_t)(row * AW + c * 4) * 4,
              A + (size_t)(m0 + row) * GK + kt * BKH + c * 8);
    }
#pragma unroll
    for (int i = 0; i < 4; i++) {
        int id = tid + i * 256;               // B: 16 rows x 64 chunks (512 halves/row)
        int row = id >> 6, c = id & 63;
        cpa16(st + (uint32_t)(A_WORDS + row * BW + c * 4) * 4,
              Wp + (size_t)(kt * 16 + row) * 8192 + (size_t)n0 * 4 + c * 8);
    }
}

__global__ __launch_bounds__(256, 2) void gemm_h(const __half* __restrict__ A,
                                                 const __half* __restrict__ Wr,
                                                 const float* __restrict__ b0p,
                                                 const float* __restrict__ b1p,
                                                 const float* __restrict__ b2p,
                                                 float* __restrict__ C0,
                                                 float* __restrict__ C1,
                                                 float* __restrict__ C2)
{
    extern __shared__ __align__(16) char smem[];
    const uint32_t sb = smem_u32(smem);
    const int z = blockIdx.z;
    const __half* Wp  = Wr + (size_t)z * DIM * DIM;
    const float* bias = (z == 0) ? b0p : (z == 1) ? b1p : b2p;
    float* C          = (z == 0) ? C0  : (z == 1) ? C1  : C2;

    const int tid  = threadIdx.x;
    const int lane = tid & 31;
    const int wid  = tid >> 5;
    const int wm   = (wid >> 1) * 32;   // 0,32,64,96
    const int wn   = (wid & 1) * 64;    // 0,64
    const int n0   = blockIdx.x * 128;
    const int m0   = blockIdx.y * 128;
    const int gq   = lane >> 2;
    const int tg   = lane & 3;

    float acc[2][8][4];
#pragma unroll
    for (int mi = 0; mi < 2; mi++)
#pragma unroll
        for (int ni = 0; ni < 8; ni++)
#pragma unroll
            for (int r = 0; r < 4; r++) acc[mi][ni][r] = 0.f;

#pragma unroll
    for (int kt = 0; kt < NSTGH; kt++) {
        load_stage_h(sb, A, Wp, m0, n0, kt, tid);
        asm volatile("cp.async.commit_group;" ::: "memory");
    }

    for (int kt = 0; kt < NTH; kt++) {
        asm volatile("cp.async.wait_group %0;" :: "n"(NSTGH - 1) : "memory");
        __syncthreads();

        const uint32_t* smw = (const uint32_t*)(smem + (kt % NSTGH) * STGB);
        const uint32_t* smb = smw + A_WORDS;

#pragma unroll
        for (int s = 0; s < 4; s++) {
            uint32_t afr[2][4];
#pragma unroll
            for (int mi = 0; mi < 2; mi++) {
                int r0 = wm + mi * 16 + gq;
                uint2 t0 = *(const uint2*)(smw + r0 * AW + s * 8 + 2 * tg);
                uint2 t1 = *(const uint2*)(smw + (r0 + 8) * AW + s * 8 + 2 * tg);
                afr[mi][0] = t0.x; afr[mi][1] = t1.x;
                afr[mi][2] = t0.y; afr[mi][3] = t1.y;
            }
#pragma unroll
            for (int ni = 0; ni < 8; ni++) {
                int nb = wn + ni * 8 + gq;
                uint2 bb = *(const uint2*)(smb + (s * 4 + tg) * BW + 2 * nb);
                mma16(acc[0][ni], afr[0], bb.x, bb.y);
                mma16(acc[1][ni], afr[1], bb.x, bb.y);
            }
        }
        __syncthreads();

        if (kt + NSTGH < NTH)
            load_stage_h(sb, A, Wp, m0, n0, kt + NSTGH, tid);
        asm volatile("cp.async.commit_group;" ::: "memory");
    }

#pragma unroll
    for (int mi = 0; mi < 2; mi++) {
        int row = m0 + wm + mi * 16 + gq;
#pragma unroll
        for (int ni = 0; ni < 8; ni++) {
            int col = n0 + wn + ni * 8 + 2 * tg;
            float2 bz = *(const float2*)(bias + col);
            float2 v0, v1;
            v0.x = acc[mi][ni][0] + bz.x; v0.y = acc[mi][ni][1] + bz.y;
            v1.x = acc[mi][ni][2] + bz.x; v1.y = acc[mi][ni][3] + bz.y;
            *(float2*)(C + (size_t)row * DIM + col)       = v0;
            *(float2*)(C + (size_t)(row + 8) * DIM + col) = v1;
        }
    }
}

// ---------------- RMSNorm + RoPE (table-driven): fp32 in, fp16 out ----------------
#define ATT_SCALE 0.08838834764831845f
__global__ __launch_bounds__(256) void rmsnorm_h(const float* __restrict__ qb,
                                                 const float* __restrict__ kb,
                                                 __half* __restrict__ qh,
                                                 __half* __restrict__ kph,
                                                 const float* __restrict__ gqw,
                                                 const float* __restrict__ gkw,
                                                 const float2* __restrict__ tab)
{
    const int t = blockIdx.x;
    const int isk = blockIdx.y;
    const float* row = (isk ? kb : qb) + (size_t)t * DIM;
    const float* g = isk ? gkw : gqw;
    const float2* cs = tab + (size_t)t * 64;

    float ss = 0.f;
    for (int i = threadIdx.x; i < DIM; i += 256) {
        float v = row[i];
        ss += v * v;
    }
#pragma unroll
    for (int off = 16; off; off >>= 1) ss += __shfl_xor_sync(0xFFFFFFFFu, ss, off);

    __shared__ float red[8];
    __shared__ float stot;
    if ((threadIdx.x & 31) == 0) red[threadIdx.x >> 5] = ss;
    __syncthreads();
    if (threadIdx.x == 0) {
        float tot = 0.f;
#pragma unroll
        for (int i = 0; i < 8; i++) tot += red[i];
        stot = tot;
    }
    __syncthreads();

    const float scale = rsqrtf(stot * (1.f / DIM) + 1e-6f);
    __half* outq = qh + (size_t)t * DIM;
    __half* outk = kph + (size_t)t * DIM;

    for (int p = threadIdx.x; p < DIM / 2; p += 256) {
        int e   = 2 * p;
        float2 t2 = cs[p & 63];
        float c = t2.x, s = t2.y;
        float x0 = row[e]     * scale * g[e];
        float x1 = row[e + 1] * scale * g[e + 1];
        float y0 = x0 * c - x1 * s;
        float y1 = x0 * s + x1 * c;
        if (!isk) {
            y0 *= ATT_SCALE;
            y1 *= ATT_SCALE;
            int pw = (e >> 1) & 7;
            int pos = (pw < 4) ? 2 * pw : 2 * pw - 7;
            int idx = (e & ~15) + pos * 2;
            *reinterpret_cast<__half2*>(outq + idx) = __floats2half2_rn(y0, y1);
        } else {
            int idx = (e & ~15) + ((e >> 1) & 3) * 4 + 2 * ((e >> 3) & 1);
            *reinterpret_cast<__half2*>(outk + idx) = __floats2half2_rn(y0, y1);
        }
    }
}

// ---------------- transpose V -> Vt[d][key'] fp16 with chunk-perm on key ----------------
__global__ __launch_bounds__(256) void transpose_vh(const float* __restrict__ V,
                                                    __half* __restrict__ Vt)
{
    __shared__ float tl[32][33];
    const int t0 = blockIdx.x * 32;
    const int d0 = blockIdx.y * 32;
    const int tx = threadIdx.x & 31, ty = threadIdx.x >> 5;
#pragma unroll
    for (int i = 0; i < 4; i++)
        tl[ty + 8 * i][tx] = V[(size_t)(t0 + ty + 8 * i) * DIM + d0 + tx];
    __syncthreads();
    const int tp = (tx & ~15) + ((tx >> 1) & 3) * 4 + 2 * ((tx >> 3) & 1) + (tx & 1);
#pragma unroll
    for (int i = 0; i < 4; i++)
        Vt[(size_t)(d0 + ty + 8 * i) * T_SEQ + t0 + tp] = __float2half_rn(tl[tx][ty + 8 * i]);
}

// ---------------- causal flash attention via fp16 mma ----------------
#define QW   72
#define KW   72
#define VW   40
#define SMK  (128 * QW)
#define KBUF (64 * KW)
#define SMV  (SMK + 2 * KBUF)
#define VBUF (128 * VW)
#define FAW  (SMV + 2 * VBUF)
#define FAB  (FAW * 4)

__device__ __forceinline__ void fa_load_h(uint32_t sb, const __half* __restrict__ Kp,
                                          const __half* __restrict__ Vt,
                                          int h, int j, int buf, int tid) {
    const int k0 = j * 64;
    uint32_t kb = sb + (uint32_t)(SMK + buf * KBUF) * 4;
    uint32_t vb = sb + (uint32_t)(SMV + buf * VBUF) * 4;
#pragma unroll
    for (int i = 0; i < 4; i++) {
        int id = tid + i * 256;
        int key = id >> 4, c = id & 15;
        cpa16(kb + (uint32_t)(key * KW + c * 4) * 4,
              Kp + (size_t)(k0 + key) * DIM + h * HD + c * 8);
    }
#pragma unroll
    for (int i = 0; i < 4; i++) {
        int id = tid + i * 256;
        int d = id >> 3, c = id & 7;
        cpa16(vb + (uint32_t)(d * VW + c * 4) * 4,
              Vt + (size_t)(h * HD + d) * T_SEQ + k0 + c * 8);
    }
}

__global__ __launch_bounds__(256) void flash_h(const __half* __restrict__ Q,
                                               const __half* __restrict__ Kp,
                                               const __half* __restrict__ Vt,
                                               __half* __restrict__ O)
{
    extern __shared__ __align__(16) char smraw[];
    const uint32_t sb = smem_u32(smraw);
    const uint32_t* smw = (const uint32_t*)smraw;
    const int qt = gridDim.x - 1 - blockIdx.x;
    const int h  = blockIdx.y;
    const int q0 = qt * 128;
    const int tid  = threadIdx.x;
    const int lane = tid & 31, wid = tid >> 5;
    const int gq = lane >> 2, tg = lane & 3;
    const int wrow = wid * 16;
    const int nkt = 2 * qt + 2;

    for (int idx = tid; idx < 2048; idx += 256) {
        int r = idx >> 4, c = idx & 15;
        cpa16(sb + (uint32_t)(r * QW + c * 4) * 4,
              Q + (size_t)(q0 + r) * DIM + h * HD + c * 8);
    }
    fa_load_h(sb, Kp, Vt, h, 0, 0, tid);
    asm volatile("cp.async.commit_group;" ::: "memory");
    asm volatile("cp.async.wait_group 0;" ::: "memory");
    __syncthreads();

    uint32_t qfr[8][4];
    {
        const uint32_t* Qp = smw + (wrow + gq) * QW;
#pragma unroll
        for (int s = 0; s < 8; s++) {
            uint2 t0 = *(const uint2*)(Qp + s * 8 + 2 * tg);
            uint2 t1 = *(const uint2*)(Qp + 8 * QW + s * 8 + 2 * tg);
            qfr[s][0] = t0.x; qfr[s][1] = t1.x;
            qfr[s][2] = t0.y; qfr[s][3] = t1.y;
        }
    }

    float oacc[16][4];
#pragma unroll
    for (int nt = 0; nt < 16; nt++)
#pragma unroll
        for (int r = 0; r < 4; r++) oacc[nt][r] = 0.f;

    float m0 = -1e30f, m1 = -1e30f, l0 = 0.f, l1 = 0.f;
    const int r0 = q0 + wrow + gq, r1 = r0 + 8;

    for (int j = 0; j < nkt; j++) {
        if (j + 1 < nkt) {
            fa_load_h(sb, Kp, Vt, h, j + 1, (j + 1) & 1, tid);
            asm volatile("cp.async.commit_group;" ::: "memory");
        }

        const int buf = j & 1;
        const int k0 = j * 64;
        const uint32_t* Kw = smw + SMK + buf * KBUF;
        const uint32_t* Vw = smw + SMV + buf * VBUF;

        float sacc[8][4];
#pragma unroll
        for (int nt = 0; nt < 8; nt++)
#pragma unroll
            for (int r = 0; r < 4; r++) sacc[nt][r] = 0.f;

#pragma unroll
        for (int s = 0; s < 8; s++) {
#pragma unroll
            for (int nt = 0; nt < 8; nt++) {
                uint2 kb2 = *(const uint2*)(Kw + (nt * 8 + gq) * KW + s * 8 + 2 * tg);
                mma16(sacc[nt], qfr[s], kb2.x, kb2.y);
            }
        }

        float mx0 = -1e30f, mx1 = -1e30f;
        if (k0 + 63 > q0) {
#pragma unroll
            for (int nt = 0; nt < 8; nt++) {
                int c0 = k0 + nt * 8 + 2 * tg;
                if (c0     > r0) sacc[nt][0] = -1e30f;
                if (c0 + 1 > r0) sacc[nt][1] = -1e30f;
                if (c0     > r1) sacc[nt][2] = -1e30f;
                if (c0 + 1 > r1) sacc[nt][3] = -1e30f;
                mx0 = fmaxf(mx0, fmaxf(sacc[nt][0], sacc[nt][1]));
                mx1 = fmaxf(mx1, fmaxf(sacc[nt][2], sacc[nt][3]));
            }
        } else {
#pragma unroll
            for (int nt = 0; nt < 8; nt++) {
                mx0 = fmaxf(mx0, fmaxf(sacc[nt][0], sacc[nt][1]));
                mx1 = fmaxf(mx1, fmaxf(sacc[nt][2], sacc[nt][3]));
            }
        }
        mx0 = fmaxf(mx0, __shfl_xor_sync(0xFFFFFFFFu, mx0, 1));
        mx0 = fmaxf(mx0, __shfl_xor_sync(0xFFFFFFFFu, mx0, 2));
        mx1 = fmaxf(mx1, __shfl_xor_sync(0xFFFFFFFFu, mx1, 1));
        mx1 = fmaxf(mx1, __shfl_xor_sync(0xFFFFFFFFu, mx1, 2));

        const float mn0 = fmaxf(m0, mx0), mn1 = fmaxf(m1, mx1);
        const float f0 = __expf(m0 - mn0), f1 = __expf(m1 - mn1);
        m0 = mn0; m1 = mn1;

        float rs0 = 0.f, rs1 = 0.f;
#pragma unroll
        for (int nt = 0; nt < 8; nt++) {
            float e0 = __expf(sacc[nt][0] - mn0);
            float e1 = __expf(sacc[nt][1] - mn0);
            float e2 = __expf(sacc[nt][2] - mn1);
            float e3 = __expf(sacc[nt][3] - mn1);
            rs0 += e0 + e1; rs1 += e2 + e3;
            sacc[nt][0] = e0; sacc[nt][1] = e1;
            sacc[nt][2] = e2; sacc[nt][3] = e3;
        }
        rs0 += __shfl_xor_sync(0xFFFFFFFFu, rs0, 1);
        rs0 += __shfl_xor_sync(0xFFFFFFFFu, rs0, 2);
        rs1 += __shfl_xor_sync(0xFFFFFFFFu, rs1, 1);
        rs1 += __shfl_xor_sync(0xFFFFFFFFu, rs1, 2);
        l0 = l0 * f0 + rs0;
        l1 = l1 * f1 + rs1;

#pragma unroll
        for (int nt = 0; nt < 16; nt++) {
            oacc[nt][0] *= f0; oacc[nt][1] *= f0;
            oacc[nt][2] *= f1; oacc[nt][3] *= f1;
        }

#pragma unroll
        for (int s = 0; s < 4; s++) {
            uint32_t pa[4];
            pa[0] = packh2(sacc[2 * s][0],     sacc[2 * s][1]);
            pa[1] = packh2(sacc[2 * s][2],     sacc[2 * s][3]);
            pa[2] = packh2(sacc[2 * s + 1][0], sacc[2 * s + 1][1]);
            pa[3] = packh2(sacc[2 * s + 1][2], sacc[2 * s + 1][3]);
#pragma unroll
            for (int nt = 0; nt < 16; nt++) {
                uint2 vb2 = *(const uint2*)(Vw + (nt * 8 + gq) * VW + s * 8 + 2 * tg);
                mma16(oacc[nt], pa, vb2.x, vb2.y);
            }
        }

        if (j + 1 < nkt)
            asm volatile("cp.async.wait_group 0;" ::: "memory");
        __syncthreads();
    }

    const float inv0 = 1.f / l0, inv1 = 1.f / l1;
#pragma unroll
    for (int nt = 0; nt < 16; nt++) {
        int wg = 64 * h + nt * 4 + tg;
        int gg = wg >> 3, pw = wg & 7;
        int pos = (pw < 4) ? 2 * pw : 2 * pw - 7;
        int idx = gg * 16 + pos * 2;
        *reinterpret_cast<__half2*>(O + (size_t)r0 * DIM + idx) =
            __floats2half2_rn(oacc[nt][0] * inv0, oacc[nt][1] * inv0);
        *reinterpret_cast<__half2*>(O + (size_t)r1 * DIM + idx) =
            __floats2half2_rn(oacc[nt][2] * inv1, oacc[nt][3] * inv1);
    }
}

// ---------------- launch ----------------
extern "C" void kernel_launch(void* const* d_in, const int* in_sizes, int n_in,
                              void* d_out, int out_size)
{
    (void)in_sizes; (void)n_in; (void)out_size;
    const float* x     = (const float*)d_in[0];
    const float* freqs = (const float*)d_in[1];
    const float* Wq    = (const float*)d_in[2];
    const float* bq    = (const float*)d_in[3];
    const float* Wk    = (const float*)d_in[4];
    const float* bk    = (const float*)d_in[5];
    const float* Wv    = (const float*)d_in[6];
    const float* bv    = (const float*)d_in[7];
    const float* Wo    = (const float*)d_in[8];
    const float* bo    = (const float*)d_in[9];
    const float* gq    = (const float*)d_in[10];
    const float* gk    = (const float*)d_in[11];

    float *q, *k, *v;
    float2* cs;
    __half *xh, *wh, *qh, *kph, *vth, *oh;
    cudaGetSymbolAddress((void**)&q,   g_q);
    cudaGetSymbolAddress((void**)&k,   g_k);
    cudaGetSymbolAddress((void**)&v,   g_v);
    cudaGetSymbolAddress((void**)&cs,  g_cs);
    cudaGetSymbolAddress((void**)&xh,  g_xh);
    cudaGetSymbolAddress((void**)&wh,  g_wh);
    cudaGetSymbolAddress((void**)&qh,  g_qh);
    cudaGetSymbolAddress((void**)&kph, g_kph);
    cudaGetSymbolAddress((void**)&vth, g_vth);
    cudaGetSymbolAddress((void**)&oh,  g_oh);

    const int gsm = NSTGH * STGB;   // 112128
    cudaFuncSetAttribute(gemm_h, cudaFuncAttributeMaxDynamicSharedMemorySize, gsm);
    cudaFuncSetAttribute(flash_h, cudaFuncAttributeMaxDynamicSharedMemorySize, FAB);

    rope_tab<<<T_SEQ * 64 / 256, 256>>>(freqs, cs);
    prep_x<<<T_SEQ * DIM / 2 / 256, 256>>>(x, xh);
    prep_w<<<dim3(DIM * DIM / 2 / 256, 1, 4), 256>>>(Wq, Wk, Wv, Wo, wh);

    dim3 qkvgrid(DIM / 128, T_SEQ / 128, 3);   // (16, 32, 3)
    gemm_h<<<qkvgrid, 256, gsm>>>(xh, wh, bq, bk, bv, q, k, v);

    rmsnorm_h<<<dim3(T_SEQ, 2), 256>>>(q, k, qh, kph, gq, gk, cs);

    transpose_vh<<<dim3(T_SEQ / 32, DIM / 32), 256>>>(v, vth);

    flash_h<<<dim3(T_SEQ / 128, NH), 256, FAB>>>(qh, kph, vth, oh);

    dim3 ogrid(DIM / 128, T_SEQ / 128, 1);     // (16, 32, 1)
    gemm_h<<<ogrid, 256, gsm>>>(oh, wh + (size_t)3 * DIM * DIM, bo, bo, bo,
                                (float*)d_out, (float*)d_out, (float*)d_out);
}